// round 5
// baseline (speedup 1.0000x reference)
#include <cuda_runtime.h>
#include <cuda_bf16.h>
#include <cstdint>

// ---------------- problem constants ----------------
#define BB    8
#define SS    2048
#define PLM   768
#define GG    256
#define NWM   50000
#define EWM   800000
#define NF    16384           // B*S
#define EF    131072
#define KSLOT 4
#define G4    (GG/4)          // 64 float4 per G-row
#define PLM4  (PLM/4)         // 192 float4 per PLM-row
#define CAT3  (PLM + 2*GG)    // 1280
#define CAT1  (GG + PLM)      // 1024

// ---------------- device scratch (no runtime alloc allowed) ----------------
// fp32 buffers
__device__ __align__(16) float g_bufH[(size_t)NWM * GG];   // GEMM fp32 outputs (WM)
__device__ __align__(16) float g_gte [(size_t)NF * GG];    // graph_text_embed
__device__ __align__(16) float g_fH  [(size_t)NF * GG];    // fstm x / scratch
__device__ __align__(16) float g_fM  [(size_t)NF * GG];    // fstm layer1 out
// bf16 split activation buffers
__device__ __align__(16) __nv_bfloat16 g_ah[(size_t)NWM * GG];
__device__ __align__(16) __nv_bfloat16 g_al[(size_t)NWM * GG];
__device__ __align__(16) __nv_bfloat16 g_c1h[(size_t)NF * CAT1];
__device__ __align__(16) __nv_bfloat16 g_c1l[(size_t)NF * CAT1];
__device__ __align__(16) __nv_bfloat16 g_c3h[(size_t)NF * CAT3];
__device__ __align__(16) __nv_bfloat16 g_c3l[(size_t)NF * CAT3];
// bf16 split transposed weights [N, K]
__device__ __align__(16) __nv_bfloat16 g_w1h[GG * GG];
__device__ __align__(16) __nv_bfloat16 g_w1l[GG * GG];
__device__ __align__(16) __nv_bfloat16 g_w2h[GG * GG];
__device__ __align__(16) __nv_bfloat16 g_w2l[GG * GG];
__device__ __align__(16) __nv_bfloat16 g_g1h[GG * GG];
__device__ __align__(16) __nv_bfloat16 g_g1l[GG * GG];
__device__ __align__(16) __nv_bfloat16 g_g2h[GG * GG];
__device__ __align__(16) __nv_bfloat16 g_g2l[GG * GG];
__device__ __align__(16) __nv_bfloat16 g_fc1h[GG * CAT1];
__device__ __align__(16) __nv_bfloat16 g_fc1l[GG * CAT1];
__device__ __align__(16) __nv_bfloat16 g_fc3h[PLM * CAT3];
__device__ __align__(16) __nv_bfloat16 g_fc3l[PLM * CAT3];
// CSR
__device__ int g_wm_rowptr[NWM + 1];
__device__ int g_wm_cur[NWM];
__device__ int g_wm_col[EWM];
__device__ int g_f_rowptr[NF + 1];
__device__ int g_f_cur[NF];
__device__ int g_f_col[EF];

// ---------------- helpers ----------------
__device__ __forceinline__ uint32_t smem_u32(const void* p) {
    uint32_t a;
    asm("{ .reg .u64 t; cvta.to.shared.u64 t, %1; cvt.u32.u64 %0, t; }" : "=r"(a) : "l"(p));
    return a;
}
__device__ __forceinline__ void cp16(uint32_t dst, const void* src, uint32_t srcsize) {
    asm volatile("cp.async.cg.shared.global [%0], [%1], 16, %2;"
                 :: "r"(dst), "l"(src), "r"(srcsize) : "memory");
}
#define CP_COMMIT() asm volatile("cp.async.commit_group;" ::: "memory")
#define CP_WAIT(n)  asm volatile("cp.async.wait_group %0;" :: "n"(n) : "memory")

__device__ __forceinline__ void ldsm4(uint32_t* r, uint32_t addr) {
    asm volatile("ldmatrix.sync.aligned.m8n8.x4.shared.b16 {%0,%1,%2,%3}, [%4];"
                 : "=r"(r[0]), "=r"(r[1]), "=r"(r[2]), "=r"(r[3]) : "r"(addr));
}
__device__ __forceinline__ void mma16816(float* c, const uint32_t* a, uint32_t b0, uint32_t b1) {
    asm volatile(
        "mma.sync.aligned.m16n8k16.row.col.f32.bf16.bf16.f32 "
        "{%0,%1,%2,%3}, {%4,%5,%6,%7}, {%8,%9}, {%0,%1,%2,%3};\n"
        : "+f"(c[0]), "+f"(c[1]), "+f"(c[2]), "+f"(c[3])
        : "r"(a[0]), "r"(a[1]), "r"(a[2]), "r"(a[3]), "r"(b0), "r"(b1));
}

__device__ __forceinline__ uint32_t packbf(float a, float b) {
    __nv_bfloat16 h0 = __float2bfloat16_rn(a);
    __nv_bfloat16 h1 = __float2bfloat16_rn(b);
    return ((uint32_t)__bfloat16_as_ushort(h1) << 16) | (uint32_t)__bfloat16_as_ushort(h0);
}
__device__ __forceinline__ void split4(float4 v, uint2& hp, uint2& lp) {
    __nv_bfloat16 h0 = __float2bfloat16_rn(v.x), h1 = __float2bfloat16_rn(v.y);
    __nv_bfloat16 h2 = __float2bfloat16_rn(v.z), h3 = __float2bfloat16_rn(v.w);
    float r0 = v.x - __bfloat162float(h0), r1 = v.y - __bfloat162float(h1);
    float r2 = v.z - __bfloat162float(h2), r3 = v.w - __bfloat162float(h3);
    hp.x = ((uint32_t)__bfloat16_as_ushort(h1) << 16) | (uint32_t)__bfloat16_as_ushort(h0);
    hp.y = ((uint32_t)__bfloat16_as_ushort(h3) << 16) | (uint32_t)__bfloat16_as_ushort(h2);
    lp.x = packbf(r0, r1);
    lp.y = packbf(r2, r3);
}

// ---------------- CSR build kernels ----------------
__global__ void zero_int_kernel(int* __restrict__ p, int n) {
    int i = blockIdx.x * blockDim.x + threadIdx.x;
    if (i < n) p[i] = 0;
}
__global__ void hist_kernel(const int* __restrict__ dst, int* __restrict__ cnt, int E) {
    int e = blockIdx.x * blockDim.x + threadIdx.x;
    if (e < E) atomicAdd(&cnt[dst[e]], 1);
}
__global__ void scan_kernel(int* __restrict__ cnt_cur, int* __restrict__ rowptr, int N, int E) {
    __shared__ int sh[1024];
    int tid = threadIdx.x;
    int chunk = (N + 1023) >> 10;
    int s0 = tid * chunk;
    int s1 = s0 + chunk; if (s1 > N) s1 = N;
    int s = 0;
    for (int i = s0; i < s1; i++) s += cnt_cur[i];
    sh[tid] = s;
    __syncthreads();
    for (int off = 1; off < 1024; off <<= 1) {
        int v = (tid >= off) ? sh[tid - off] : 0;
        __syncthreads();
        sh[tid] += v;
        __syncthreads();
    }
    int run = sh[tid] - s;
    for (int i = s0; i < s1; i++) {
        int c = cnt_cur[i];
        rowptr[i]  = run;
        cnt_cur[i] = run;
        run += c;
    }
    if (tid == 0) rowptr[N] = E;
}
__global__ void fill_kernel(const int* __restrict__ src, const int* __restrict__ dst,
                            int* __restrict__ cur, int* __restrict__ col, int E) {
    int e = blockIdx.x * blockDim.x + threadIdx.x;
    if (e < E) {
        int d = dst[e];
        int p = atomicAdd(&cur[d], 1);
        col[p] = src[e];
    }
}

// ---------------- graph / gather kernels (split-bf16 outputs) ----------------
__global__ void spmm_split_kernel(const float4* __restrict__ h,
                                  const int* __restrict__ rowptr,
                                  const int* __restrict__ col,
                                  __nv_bfloat16* __restrict__ oh,
                                  __nv_bfloat16* __restrict__ ol, int n) {
    int node = blockIdx.x * blockDim.y + threadIdx.y;
    if (node >= n) return;
    int x = threadIdx.x;  // 0..63
    float4 acc = h[(size_t)node * G4 + x];
    int e  = rowptr[node];
    int e1 = rowptr[node + 1];
    for (; e < e1; ++e) {
        int s = __ldg(&col[e]);
        float4 v = __ldg(&h[(size_t)s * G4 + x]);
        acc.x += v.x; acc.y += v.y; acc.z += v.z; acc.w += v.w;
    }
    uint2 hp, lp;
    split4(acc, hp, lp);
    *(uint2*)(oh + (size_t)node * GG + 4 * x) = hp;
    *(uint2*)(ol + (size_t)node * GG + 4 * x) = lp;
}

// tmp[row] = sum_k ge[t2n[row*4+k]]; write split into cat1 @col0 and cat3 @col768
__global__ void gather4sum_split_kernel(const float4* __restrict__ ge,
                                        const int* __restrict__ t2n,
                                        __nv_bfloat16* __restrict__ c1h, __nv_bfloat16* __restrict__ c1l,
                                        __nv_bfloat16* __restrict__ c3h, __nv_bfloat16* __restrict__ c3l,
                                        int rows) {
    int row = blockIdx.x * blockDim.y + threadIdx.y;
    if (row >= rows) return;
    int x = threadIdx.x;
    float4 acc = make_float4(0.f, 0.f, 0.f, 0.f);
#pragma unroll
    for (int k = 0; k < KSLOT; k++) {
        int idx = __ldg(&t2n[row * KSLOT + k]);
        float4 v = __ldg(&ge[(size_t)idx * G4 + x]);
        acc.x += v.x; acc.y += v.y; acc.z += v.z; acc.w += v.w;
    }
    uint2 hp, lp;
    split4(acc, hp, lp);
    *(uint2*)(c1h + (size_t)row * CAT1 + 4 * x) = hp;
    *(uint2*)(c1l + (size_t)row * CAT1 + 4 * x) = lp;
    *(uint2*)(c3h + (size_t)row * CAT3 + PLM + 4 * x) = hp;
    *(uint2*)(c3l + (size_t)row * CAT3 + PLM + 4 * x) = lp;
}

__global__ void gather_rows_kernel(const float4* __restrict__ src,
                                   const int* __restrict__ ids,
                                   float4* __restrict__ out, int rows) {
    int row = blockIdx.x * blockDim.y + threadIdx.y;
    if (row >= rows) return;
    int id = ids[row];
    out[(size_t)row * G4 + threadIdx.x] = src[(size_t)id * G4 + threadIdx.x];
}

// text fp32 -> split bf16 into cat1 @col 256 and cat3 @col 0
__global__ void textconv_kernel(const float4* __restrict__ text,
                                __nv_bfloat16* __restrict__ c1h, __nv_bfloat16* __restrict__ c1l,
                                __nv_bfloat16* __restrict__ c3h, __nv_bfloat16* __restrict__ c3l,
                                int rows) {
    int idx = blockIdx.x * blockDim.x + threadIdx.x;
    if (idx >= rows * PLM4) return;
    int row = idx / PLM4;
    int c   = idx - row * PLM4;
    uint2 hp, lp;
    split4(text[idx], hp, lp);
    *(uint2*)(c1h + (size_t)row * CAT1 + GG + 4 * c) = hp;
    *(uint2*)(c1l + (size_t)row * CAT1 + GG + 4 * c) = lp;
    *(uint2*)(c3h + (size_t)row * CAT3 + 4 * c) = hp;
    *(uint2*)(c3l + (size_t)row * CAT3 + 4 * c) = lp;
}

// weight [K,N] fp32 -> transposed [N,K] hi/lo bf16 (tiled transpose)
__global__ void wconv_kernel(const float* __restrict__ W,
                             __nv_bfloat16* __restrict__ Wh, __nv_bfloat16* __restrict__ Wl,
                             int Kd, int Nd) {
    __shared__ float t[32][33];
    int kb = blockIdx.y * 32, nb = blockIdx.x * 32;
#pragma unroll
    for (int j = 0; j < 32; j += 8) {
        int k = kb + threadIdx.y + j, n = nb + threadIdx.x;
        t[threadIdx.y + j][threadIdx.x] = W[(size_t)k * Nd + n];
    }
    __syncthreads();
#pragma unroll
    for (int j = 0; j < 32; j += 8) {
        int n = nb + threadIdx.y + j, k = kb + threadIdx.x;
        float x = t[threadIdx.x][threadIdx.y + j];
        __nv_bfloat16 h = __float2bfloat16_rn(x);
        Wh[(size_t)n * Kd + k] = h;
        Wl[(size_t)n * Kd + k] = __float2bfloat16_rn(x - __bfloat162float(h));
    }
}

// ---------------- legacy-MMA split-bf16 GEMM ----------------
// D[M,N] = A @ B^T + bias (3-pass hi/lo). A: [M,K] bf16 hi/lo K-major,
// B: [N,K] bf16 hi/lo K-major (pre-transposed weights).
// 128x128 CTA tile, BK=32, 8 warps (4m x 2n), warp tile 32x64,
// cp.async double-buffered staging, ldmatrix fragments, mma.m16n8k16.bf16.
// Output fp32 (Cf) or split bf16 (Ch/Cl). N%128==0, K%32==0; M arbitrary.
#define RS     80                    // padded smem row stride (bytes) for 64B payload
#define TILEB  (128 * RS)            // 10240 per tile
#define SOFF(b, t) (((b) * 4 + (t)) * TILEB)
#define GEMM_SMEM (8 * TILEB)        // 81920

__global__ __launch_bounds__(256, 1)
void mgemm2_kernel(const __nv_bfloat16* __restrict__ Ah, const __nv_bfloat16* __restrict__ Al,
                   const __nv_bfloat16* __restrict__ Bh, const __nv_bfloat16* __restrict__ Bl,
                   const float* __restrict__ bias,
                   float* __restrict__ Cf, __nv_bfloat16* __restrict__ Ch,
                   __nv_bfloat16* __restrict__ Cl,
                   int ldc, int M, int N, int K, int dorelu) {
    extern __shared__ char smem[];
    const uint32_t sb = smem_u32(smem);
    const int tid = threadIdx.x, lane = tid & 31, wid = tid >> 5;
    const int wm = wid & 3, wn = wid >> 2;
    const int bm = blockIdx.y * 128, bn = blockIdx.x * 128;
    const int g = lane >> 2, tg = lane & 3;

    // ---- staging geometry: thread -> (row, two 16B chunks) ----
    const int srow = tid >> 1;           // 0..127
    const int sc   = (tid & 1) * 2;      // chunk 0 or 2
    const int arow = bm + srow;
    const bool aok = arow < M;
    const int arA  = aok ? arow : 0;
    const uint32_t asz = aok ? 16u : 0u;
    const int brow = bn + srow;
    const uint32_t doff = srow * RS + sc * 16;

    auto stage = [&](int kt, int b) {
        const size_t ko = (size_t)kt * 32 + sc * 8;      // bf16 index
        const __nv_bfloat16* pAh = Ah + (size_t)arA * K + ko;
        const __nv_bfloat16* pAl = Al + (size_t)arA * K + ko;
        const __nv_bfloat16* pBh = Bh + (size_t)brow * K + ko;
        const __nv_bfloat16* pBl = Bl + (size_t)brow * K + ko;
        cp16(sb + SOFF(b, 0) + doff,      pAh,     asz);
        cp16(sb + SOFF(b, 0) + doff + 16, pAh + 8, asz);
        cp16(sb + SOFF(b, 1) + doff,      pAl,     asz);
        cp16(sb + SOFF(b, 1) + doff + 16, pAl + 8, asz);
        cp16(sb + SOFF(b, 2) + doff,      pBh,     16u);
        cp16(sb + SOFF(b, 2) + doff + 16, pBh + 8, 16u);
        cp16(sb + SOFF(b, 3) + doff,      pBl,     16u);
        cp16(sb + SOFF(b, 3) + doff + 16, pBl + 8, 16u);
    };

    // ---- fragment addresses (per-lane, constant across loop) ----
    const uint32_t aro = (wm * 32 + (lane & 7) + ((lane >> 3) & 1) * 8) * RS;
    const uint32_t ako = ((lane >> 4) & 1) * 16;
    const uint32_t bro = (wn * 64 + (lane & 7) + ((lane >> 4) & 1) * 8) * RS;
    const uint32_t bko = ((lane >> 3) & 1) * 16;

    float acc[2][8][4];
#pragma unroll
    for (int i = 0; i < 2; i++)
#pragma unroll
        for (int j = 0; j < 8; j++)
#pragma unroll
            for (int q = 0; q < 4; q++) acc[i][j][q] = 0.f;

    const int nk = K >> 5;
    stage(0, 0);
    CP_COMMIT();

    for (int t = 0; t < nk; t++) {
        const int b = t & 1;
        if (t + 1 < nk) {
            stage(t + 1, b ^ 1);
            CP_COMMIT();
            CP_WAIT(1);
        } else {
            CP_WAIT(0);
        }
        __syncthreads();

        const uint32_t baseAH = sb + SOFF(b, 0);
        const uint32_t baseAL = sb + SOFF(b, 1);
        const uint32_t baseBH = sb + SOFF(b, 2);
        const uint32_t baseBL = sb + SOFF(b, 3);

#pragma unroll
        for (int s = 0; s < 2; s++) {
            const uint32_t kb = s * 32;
            uint32_t ah[2][4], al[2][4], bh[8][2], bl[8][2];
#pragma unroll
            for (int mt = 0; mt < 2; mt++) {
                ldsm4(ah[mt], baseAH + aro + mt * (16 * RS) + kb + ako);
                ldsm4(al[mt], baseAL + aro + mt * (16 * RS) + kb + ako);
            }
#pragma unroll
            for (int p = 0; p < 4; p++) {
                uint32_t r[4];
                ldsm4(r, baseBH + bro + p * (16 * RS) + kb + bko);
                bh[2 * p][0] = r[0]; bh[2 * p][1] = r[1];
                bh[2 * p + 1][0] = r[2]; bh[2 * p + 1][1] = r[3];
                ldsm4(r, baseBL + bro + p * (16 * RS) + kb + bko);
                bl[2 * p][0] = r[0]; bl[2 * p][1] = r[1];
                bl[2 * p + 1][0] = r[2]; bl[2 * p + 1][1] = r[3];
            }
#pragma unroll
            for (int nt = 0; nt < 8; nt++)
#pragma unroll
                for (int mt = 0; mt < 2; mt++) {
                    mma16816(acc[mt][nt], ah[mt], bh[nt][0], bh[nt][1]);  // hi*hi
                    mma16816(acc[mt][nt], ah[mt], bl[nt][0], bl[nt][1]);  // hi*lo
                    mma16816(acc[mt][nt], al[mt], bh[nt][0], bh[nt][1]);  // lo*hi
                }
        }
        __syncthreads();
    }

    // ---- epilogue: bias + optional relu, fp32 or split-bf16 output ----
#pragma unroll
    for (int nt = 0; nt < 8; nt++) {
        const int col = bn + wn * 64 + nt * 8 + 2 * tg;
        float2 bv = *(const float2*)&bias[col];
#pragma unroll
        for (int mt = 0; mt < 2; mt++) {
            const int row0 = bm + wm * 32 + mt * 16 + g;
            float v0 = acc[mt][nt][0] + bv.x;
            float v1 = acc[mt][nt][1] + bv.y;
            float v2 = acc[mt][nt][2] + bv.x;
            float v3 = acc[mt][nt][3] + bv.y;
            if (dorelu) {
                v0 = fmaxf(v0, 0.f); v1 = fmaxf(v1, 0.f);
                v2 = fmaxf(v2, 0.f); v3 = fmaxf(v3, 0.f);
            }
            if (Ch) {
                if (row0 < M) {
                    __nv_bfloat16 h0 = __float2bfloat16_rn(v0);
                    __nv_bfloat16 h1 = __float2bfloat16_rn(v1);
                    *(uint32_t*)(Ch + (size_t)row0 * ldc + col) =
                        ((uint32_t)__bfloat16_as_ushort(h1) << 16) | (uint32_t)__bfloat16_as_ushort(h0);
                    *(uint32_t*)(Cl + (size_t)row0 * ldc + col) =
                        packbf(v0 - __bfloat162float(h0), v1 - __bfloat162float(h1));
                }
                if (row0 + 8 < M) {
                    __nv_bfloat16 h2 = __float2bfloat16_rn(v2);
                    __nv_bfloat16 h3 = __float2bfloat16_rn(v3);
                    *(uint32_t*)(Ch + (size_t)(row0 + 8) * ldc + col) =
                        ((uint32_t)__bfloat16_as_ushort(h3) << 16) | (uint32_t)__bfloat16_as_ushort(h2);
                    *(uint32_t*)(Cl + (size_t)(row0 + 8) * ldc + col) =
                        packbf(v2 - __bfloat162float(h2), v3 - __bfloat162float(h3));
                }
            } else {
                if (row0 < M)
                    *(float2*)&Cf[(size_t)row0 * ldc + col] = make_float2(v0, v1);
                if (row0 + 8 < M)
                    *(float2*)&Cf[(size_t)(row0 + 8) * ldc + col] = make_float2(v2, v3);
            }
        }
    }
}

// ---------------- host launcher ----------------
static void mgemm2(const __nv_bfloat16* Ah, const __nv_bfloat16* Al,
                   const __nv_bfloat16* Bh, const __nv_bfloat16* Bl,
                   const float* bias, float* Cf, __nv_bfloat16* Ch, __nv_bfloat16* Cl,
                   int ldc, int M, int N, int K, int relu) {
    dim3 grid(N / 128, (M + 127) / 128);
    mgemm2_kernel<<<grid, 256, GEMM_SMEM>>>(Ah, Al, Bh, Bl, bias, Cf, Ch, Cl, ldc, M, N, K, relu);
}

extern "C" void kernel_launch(void* const* d_in, const int* in_sizes, int n_in,
                              void* d_out, int out_size) {
    (void)in_sizes; (void)n_in; (void)out_size;

    const float* text   = (const float*)d_in[0];
    const float* wm_x   = (const float*)d_in[1];
    const int*   wm_ei  = (const int*)  d_in[2];
    const int*   t2n    = (const int*)  d_in[3];
    const int*   fids   = (const int*)  d_in[4];
    const int*   f_ei   = (const int*)  d_in[5];
    // d_in[6] extra_emb: unreachable (indices always >= 2)
    const float* wm_W1  = (const float*)d_in[7];
    const float* wm_b1  = (const float*)d_in[8];
    const float* wm_W2  = (const float*)d_in[9];
    const float* wm_b2  = (const float*)d_in[10];
    const float* f_W1   = (const float*)d_in[11];
    const float* f_b1   = (const float*)d_in[12];
    const float* f_W2   = (const float*)d_in[13];
    const float* f_b2   = (const float*)d_in[14];
    const float* fc1_W  = (const float*)d_in[15];
    const float* fc1_b  = (const float*)d_in[16];
    const float* fc3_W  = (const float*)d_in[17];
    const float* fc3_b  = (const float*)d_in[18];
    float* out = (float*)d_out;

    cudaFuncSetAttribute(mgemm2_kernel, cudaFuncAttributeMaxDynamicSharedMemorySize, GEMM_SMEM);

    float *bufH, *gte, *fH, *fM;
    __nv_bfloat16 *ah, *al, *c1h, *c1l, *c3h, *c3l;
    __nv_bfloat16 *w1h, *w1l, *w2h, *w2l, *gh1, *gl1, *gh2, *gl2, *p1h, *p1l, *p3h, *p3l;
    int *wrp, *wcur, *wcol, *frp, *fcur, *fcol;
    cudaGetSymbolAddress((void**)&bufH, g_bufH);
    cudaGetSymbolAddress((void**)&gte,  g_gte);
    cudaGetSymbolAddress((void**)&fH,   g_fH);
    cudaGetSymbolAddress((void**)&fM,   g_fM);
    cudaGetSymbolAddress((void**)&ah,   g_ah);
    cudaGetSymbolAddress((void**)&al,   g_al);
    cudaGetSymbolAddress((void**)&c1h,  g_c1h);
    cudaGetSymbolAddress((void**)&c1l,  g_c1l);
    cudaGetSymbolAddress((void**)&c3h,  g_c3h);
    cudaGetSymbolAddress((void**)&c3l,  g_c3l);
    cudaGetSymbolAddress((void**)&w1h,  g_w1h);
    cudaGetSymbolAddress((void**)&w1l,  g_w1l);
    cudaGetSymbolAddress((void**)&w2h,  g_w2h);
    cudaGetSymbolAddress((void**)&w2l,  g_w2l);
    cudaGetSymbolAddress((void**)&gh1,  g_g1h);
    cudaGetSymbolAddress((void**)&gl1,  g_g1l);
    cudaGetSymbolAddress((void**)&gh2,  g_g2h);
    cudaGetSymbolAddress((void**)&gl2,  g_g2l);
    cudaGetSymbolAddress((void**)&p1h,  g_fc1h);
    cudaGetSymbolAddress((void**)&p1l,  g_fc1l);
    cudaGetSymbolAddress((void**)&p3h,  g_fc3h);
    cudaGetSymbolAddress((void**)&p3l,  g_fc3l);
    cudaGetSymbolAddress((void**)&wrp,  g_wm_rowptr);
    cudaGetSymbolAddress((void**)&wcur, g_wm_cur);
    cudaGetSymbolAddress((void**)&wcol, g_wm_col);
    cudaGetSymbolAddress((void**)&frp,  g_f_rowptr);
    cudaGetSymbolAddress((void**)&fcur, g_f_cur);
    cudaGetSymbolAddress((void**)&fcol, g_f_col);

    const dim3 bSp(64, 4);
    const dim3 wcb(32, 8);

    // ===== weight convert + transpose (once per call) =====
    wconv_kernel<<<dim3(GG / 32, GG / 32), wcb>>>(wm_W1, w1h, w1l, GG, GG);
    wconv_kernel<<<dim3(GG / 32, GG / 32), wcb>>>(wm_W2, w2h, w2l, GG, GG);
    wconv_kernel<<<dim3(GG / 32, GG / 32), wcb>>>(f_W1, gh1, gl1, GG, GG);
    wconv_kernel<<<dim3(GG / 32, GG / 32), wcb>>>(f_W2, gh2, gl2, GG, GG);
    wconv_kernel<<<dim3(GG / 32, CAT1 / 32), wcb>>>(fc1_W, p1h, p1l, CAT1, GG);
    wconv_kernel<<<dim3(PLM / 32, CAT3 / 32), wcb>>>(fc3_W, p3h, p3l, CAT3, PLM);

    // ===== WM CSR build (rows = dst, cols = src) =====
    zero_int_kernel<<<(NWM + 255) / 256, 256>>>(wcur, NWM);
    hist_kernel<<<(EWM + 255) / 256, 256>>>(wm_ei + EWM, wcur, EWM);
    scan_kernel<<<1, 1024>>>(wcur, wrp, NWM, EWM);
    fill_kernel<<<(EWM + 255) / 256, 256>>>(wm_ei, wm_ei + EWM, wcur, wcol, EWM);

    // ===== WM GNN: 2 layers =====
    spmm_split_kernel<<<(NWM + 3) / 4, bSp>>>((const float4*)wm_x, wrp, wcol, ah, al, NWM);
    mgemm2(ah, al, w1h, w1l, wm_b1, bufH, nullptr, nullptr, GG, NWM, GG, GG, 1);
    spmm_split_kernel<<<(NWM + 3) / 4, bSp>>>((const float4*)bufH, wrp, wcol, ah, al, NWM);
    mgemm2(ah, al, w2h, w2l, wm_b2, bufH, nullptr, nullptr, GG, NWM, GG, GG, 1);
    // bufH = graph_embeddings [NWM, G]

    // ===== token concept sum + text conversion -> cat buffers =====
    gather4sum_split_kernel<<<(NF + 3) / 4, bSp>>>((const float4*)bufH, t2n,
                                                   c1h, c1l, c3h, c3l, NF);
    textconv_kernel<<<(NF * PLM4 + 255) / 256, 256>>>((const float4*)text, c1h, c1l, c3h, c3l, NF);

    // ===== fc1 =====
    mgemm2(c1h, c1l, p1h, p1l, fc1_b, gte, nullptr, nullptr, GG, NF, GG, CAT1, 0);

    // ===== FSTM: gather + CSR + 2 layers =====
    gather_rows_kernel<<<(NF + 3) / 4, bSp>>>((const float4*)gte, fids, (float4*)fH, NF);

    zero_int_kernel<<<(NF + 255) / 256, 256>>>(fcur, NF);
    hist_kernel<<<(EF + 255) / 256, 256>>>(f_ei + EF, fcur, EF);
    scan_kernel<<<1, 1024>>>(fcur, frp, NF, EF);
    fill_kernel<<<(EF + 255) / 256, 256>>>(f_ei, f_ei + EF, fcur, fcol, EF);

    spmm_split_kernel<<<(NF + 3) / 4, bSp>>>((const float4*)fH, frp, fcol, ah, al, NF);
    mgemm2(ah, al, gh1, gl1, f_b1, fM, nullptr, nullptr, GG, NF, GG, GG, 1);
    spmm_split_kernel<<<(NF + 3) / 4, bSp>>>((const float4*)fM, frp, fcol, ah, al, NF);
    // fstm layer2 output written split straight into cat3 @ col 1024
    mgemm2(ah, al, gh2, gl2, f_b2, nullptr, c3h + (PLM + GG), c3l + (PLM + GG),
           CAT3, NF, GG, GG, 1);

    // ===== fc3 -> out =====
    mgemm2(c3h, c3l, p3h, p3l, fc3_b, out, nullptr, nullptr, PLM, NF, PLM, CAT3, 0);
}

// round 6
// speedup vs baseline: 1.1398x; 1.1398x over previous
#include <cuda_runtime.h>
#include <cuda_fp16.h>
#include <cstdint>

// ---------------- problem constants ----------------
#define PLM   768
#define GG    256
#define NWM   50000
#define EWM   800000
#define NF    16384           // B*S
#define EF    131072
#define KSLOT 4
#define G4    (GG/4)          // 64 float4 per G-row
#define PLM4  (PLM/4)         // 192 float4 per PLM-row
#define CAT3  (PLM + 2*GG)    // 1280
#define CAT1  (GG + PLM)      // 1024

// ---------------- device scratch (no runtime alloc allowed) ----------------
// fp32 buffers
__device__ __align__(16) float g_bufH[(size_t)NWM * GG];   // t = h @ W   (WM, reused)
__device__ __align__(16) float g_bufG[(size_t)NWM * GG];   // graph embeddings (fp32)
__device__ __align__(16) float g_fM  [(size_t)NWM * GG];   // fstm t buffers (oversized ok)
__device__ __align__(16) float g_fH  [(size_t)NF * GG];
__device__ __align__(16) float g_zerob[PLM];               // zero bias (BSS -> zeros)
// fp16 split activation buffers
__device__ __align__(16) __half g_ah [(size_t)NWM * GG];
__device__ __align__(16) __half g_al [(size_t)NWM * GG];
__device__ __align__(16) __half g_gteh[(size_t)NF * GG];
__device__ __align__(16) __half g_gtel[(size_t)NF * GG];
__device__ __align__(16) __half g_c1h[(size_t)NF * CAT1];
__device__ __align__(16) __half g_c1l[(size_t)NF * CAT1];
__device__ __align__(16) __half g_c3h[(size_t)NF * CAT3];
__device__ __align__(16) __half g_c3l[(size_t)NF * CAT3];
// fp16 split transposed weights [N, K]
__device__ __align__(16) __half g_w1h[GG * GG];
__device__ __align__(16) __half g_w1l[GG * GG];
__device__ __align__(16) __half g_w2h[GG * GG];
__device__ __align__(16) __half g_w2l[GG * GG];
__device__ __align__(16) __half g_g1h[GG * GG];
__device__ __align__(16) __half g_g1l[GG * GG];
__device__ __align__(16) __half g_g2h[GG * GG];
__device__ __align__(16) __half g_g2l[GG * GG];
__device__ __align__(16) __half g_fc1h[GG * CAT1];
__device__ __align__(16) __half g_fc1l[GG * CAT1];
__device__ __align__(16) __half g_fc3h[PLM * CAT3];
__device__ __align__(16) __half g_fc3l[PLM * CAT3];
// CSR
__device__ int g_wm_rowptr[NWM + 1];
__device__ int g_wm_cur[NWM];
__device__ int g_wm_col[EWM];
__device__ int g_f_rowptr[NF + 1];
__device__ int g_f_cur[NF];
__device__ int g_f_col[EF];

// ---------------- helpers ----------------
__device__ __forceinline__ uint32_t smem_u32(const void* p) {
    uint32_t a;
    asm("{ .reg .u64 t; cvta.to.shared.u64 t, %1; cvt.u32.u64 %0, t; }" : "=r"(a) : "l"(p));
    return a;
}
__device__ __forceinline__ void cp16(uint32_t dst, const void* src, uint32_t srcsize) {
    asm volatile("cp.async.cg.shared.global [%0], [%1], 16, %2;"
                 :: "r"(dst), "l"(src), "r"(srcsize) : "memory");
}
#define CP_COMMIT() asm volatile("cp.async.commit_group;" ::: "memory")
#define CP_WAIT(n)  asm volatile("cp.async.wait_group %0;" :: "n"(n) : "memory")

__device__ __forceinline__ void ldsm4(uint32_t* r, uint32_t addr) {
    asm volatile("ldmatrix.sync.aligned.m8n8.x4.shared.b16 {%0,%1,%2,%3}, [%4];"
                 : "=r"(r[0]), "=r"(r[1]), "=r"(r[2]), "=r"(r[3]) : "r"(addr));
}
__device__ __forceinline__ void mma16816(float* c, const uint32_t* a, uint32_t b0, uint32_t b1) {
    asm volatile(
        "mma.sync.aligned.m16n8k16.row.col.f32.f16.f16.f32 "
        "{%0,%1,%2,%3}, {%4,%5,%6,%7}, {%8,%9}, {%0,%1,%2,%3};\n"
        : "+f"(c[0]), "+f"(c[1]), "+f"(c[2]), "+f"(c[3])
        : "r"(a[0]), "r"(a[1]), "r"(a[2]), "r"(a[3]), "r"(b0), "r"(b1));
}

__device__ __forceinline__ uint32_t packh(float a, float b) {
    __half ha = __float2half_rn(a), hb = __float2half_rn(b);
    return ((uint32_t)__half_as_ushort(hb) << 16) | (uint32_t)__half_as_ushort(ha);
}
__device__ __forceinline__ void split4h(float4 v, uint2& hp, uint2& lp) {
    __half h0 = __float2half_rn(v.x), h1 = __float2half_rn(v.y);
    __half h2 = __float2half_rn(v.z), h3 = __float2half_rn(v.w);
    hp.x = ((uint32_t)__half_as_ushort(h1) << 16) | (uint32_t)__half_as_ushort(h0);
    hp.y = ((uint32_t)__half_as_ushort(h3) << 16) | (uint32_t)__half_as_ushort(h2);
    lp.x = packh(v.x - __half2float(h0), v.y - __half2float(h1));
    lp.y = packh(v.z - __half2float(h2), v.w - __half2float(h3));
}

// ---------------- CSR build kernels ----------------
__global__ void zero_int_kernel(int* __restrict__ p, int n) {
    int i = blockIdx.x * blockDim.x + threadIdx.x;
    if (i < n) p[i] = 0;
}
__global__ void hist_kernel(const int* __restrict__ dst, int* __restrict__ cnt, int E) {
    int e = blockIdx.x * blockDim.x + threadIdx.x;
    if (e < E) atomicAdd(&cnt[dst[e]], 1);
}
__global__ void scan_kernel(int* __restrict__ cnt_cur, int* __restrict__ rowptr, int N, int E) {
    __shared__ int sh[1024];
    int tid = threadIdx.x;
    int chunk = (N + 1023) >> 10;
    int s0 = tid * chunk;
    int s1 = s0 + chunk; if (s1 > N) s1 = N;
    int s = 0;
    for (int i = s0; i < s1; i++) s += cnt_cur[i];
    sh[tid] = s;
    __syncthreads();
    for (int off = 1; off < 1024; off <<= 1) {
        int v = (tid >= off) ? sh[tid - off] : 0;
        __syncthreads();
        sh[tid] += v;
        __syncthreads();
    }
    int run = sh[tid] - s;
    for (int i = s0; i < s1; i++) {
        int c = cnt_cur[i];
        rowptr[i]  = run;
        cnt_cur[i] = run;
        run += c;
    }
    if (tid == 0) rowptr[N] = E;
}
__global__ void fill_kernel(const int* __restrict__ src, const int* __restrict__ dst,
                            int* __restrict__ cur, int* __restrict__ col, int E) {
    int e = blockIdx.x * blockDim.x + threadIdx.x;
    if (e < E) {
        int d = dst[e];
        int p = atomicAdd(&cur[d], 1);
        col[p] = src[e];
    }
}

// ---------------- elementwise / gather kernels ----------------
// fp32 [rows, G] -> split fp16 hi/lo
__global__ void split_x_kernel(const float4* __restrict__ x,
                               __half* __restrict__ oh, __half* __restrict__ ol, int n4) {
    int idx = blockIdx.x * blockDim.x + threadIdx.x;
    if (idx >= n4) return;
    uint2 hp, lp;
    split4h(x[idx], hp, lp);
    *(uint2*)(oh + 4 * (size_t)idx) = hp;
    *(uint2*)(ol + 4 * (size_t)idx) = lp;
}

// aggregate post-GEMM: v = relu(t[n] + sum t[src] + bias); write split (strided)
__global__ void spmm_post_split_kernel(const float4* __restrict__ t,
                                       const int* __restrict__ rowptr,
                                       const int* __restrict__ col,
                                       const float* __restrict__ bias,
                                       __half* __restrict__ oh, __half* __restrict__ ol,
                                       size_t ldo, size_t coff, int n) {
    int node = blockIdx.x * blockDim.y + threadIdx.y;
    if (node >= n) return;
    int x = threadIdx.x;  // 0..63
    float4 acc = t[(size_t)node * G4 + x];
    int e  = rowptr[node];
    int e1 = rowptr[node + 1];
    for (; e + 4 <= e1; e += 4) {
        int s0 = __ldg(&col[e]), s1 = __ldg(&col[e + 1]);
        int s2 = __ldg(&col[e + 2]), s3 = __ldg(&col[e + 3]);
        float4 v0 = __ldg(&t[(size_t)s0 * G4 + x]);
        float4 v1 = __ldg(&t[(size_t)s1 * G4 + x]);
        float4 v2 = __ldg(&t[(size_t)s2 * G4 + x]);
        float4 v3 = __ldg(&t[(size_t)s3 * G4 + x]);
        acc.x += v0.x + v1.x + v2.x + v3.x;
        acc.y += v0.y + v1.y + v2.y + v3.y;
        acc.z += v0.z + v1.z + v2.z + v3.z;
        acc.w += v0.w + v1.w + v2.w + v3.w;
    }
    for (; e < e1; ++e) {
        int s = __ldg(&col[e]);
        float4 v = __ldg(&t[(size_t)s * G4 + x]);
        acc.x += v.x; acc.y += v.y; acc.z += v.z; acc.w += v.w;
    }
    float4 bv = *(const float4*)&bias[4 * x];
    acc.x = fmaxf(acc.x + bv.x, 0.f);
    acc.y = fmaxf(acc.y + bv.y, 0.f);
    acc.z = fmaxf(acc.z + bv.z, 0.f);
    acc.w = fmaxf(acc.w + bv.w, 0.f);
    uint2 hp, lp;
    split4h(acc, hp, lp);
    *(uint2*)(oh + (size_t)node * ldo + coff + 4 * x) = hp;
    *(uint2*)(ol + (size_t)node * ldo + coff + 4 * x) = lp;
}

// aggregate post-GEMM, fp32 output
__global__ void spmm_post_f32_kernel(const float4* __restrict__ t,
                                     const int* __restrict__ rowptr,
                                     const int* __restrict__ col,
                                     const float* __restrict__ bias,
                                     float4* __restrict__ out, int n) {
    int node = blockIdx.x * blockDim.y + threadIdx.y;
    if (node >= n) return;
    int x = threadIdx.x;
    float4 acc = t[(size_t)node * G4 + x];
    int e  = rowptr[node];
    int e1 = rowptr[node + 1];
    for (; e + 4 <= e1; e += 4) {
        int s0 = __ldg(&col[e]), s1 = __ldg(&col[e + 1]);
        int s2 = __ldg(&col[e + 2]), s3 = __ldg(&col[e + 3]);
        float4 v0 = __ldg(&t[(size_t)s0 * G4 + x]);
        float4 v1 = __ldg(&t[(size_t)s1 * G4 + x]);
        float4 v2 = __ldg(&t[(size_t)s2 * G4 + x]);
        float4 v3 = __ldg(&t[(size_t)s3 * G4 + x]);
        acc.x += v0.x + v1.x + v2.x + v3.x;
        acc.y += v0.y + v1.y + v2.y + v3.y;
        acc.z += v0.z + v1.z + v2.z + v3.z;
        acc.w += v0.w + v1.w + v2.w + v3.w;
    }
    for (; e < e1; ++e) {
        int s = __ldg(&col[e]);
        float4 v = __ldg(&t[(size_t)s * G4 + x]);
        acc.x += v.x; acc.y += v.y; acc.z += v.z; acc.w += v.w;
    }
    float4 bv = *(const float4*)&bias[4 * x];
    acc.x = fmaxf(acc.x + bv.x, 0.f);
    acc.y = fmaxf(acc.y + bv.y, 0.f);
    acc.z = fmaxf(acc.z + bv.z, 0.f);
    acc.w = fmaxf(acc.w + bv.w, 0.f);
    out[(size_t)node * G4 + x] = acc;
}

// tmp[row] = sum_k ge[t2n[row*4+k]]; write split into cat1 @col0 and cat3 @col768
__global__ void gather4sum_split_kernel(const float4* __restrict__ ge,
                                        const int* __restrict__ t2n,
                                        __half* __restrict__ c1h, __half* __restrict__ c1l,
                                        __half* __restrict__ c3h, __half* __restrict__ c3l,
                                        int rows) {
    int row = blockIdx.x * blockDim.y + threadIdx.y;
    if (row >= rows) return;
    int x = threadIdx.x;
    float4 acc = make_float4(0.f, 0.f, 0.f, 0.f);
#pragma unroll
    for (int k = 0; k < KSLOT; k++) {
        int idx = __ldg(&t2n[row * KSLOT + k]);
        float4 v = __ldg(&ge[(size_t)idx * G4 + x]);
        acc.x += v.x; acc.y += v.y; acc.z += v.z; acc.w += v.w;
    }
    uint2 hp, lp;
    split4h(acc, hp, lp);
    *(uint2*)(c1h + (size_t)row * CAT1 + 4 * x) = hp;
    *(uint2*)(c1l + (size_t)row * CAT1 + 4 * x) = lp;
    *(uint2*)(c3h + (size_t)row * CAT3 + PLM + 4 * x) = hp;
    *(uint2*)(c3l + (size_t)row * CAT3 + PLM + 4 * x) = lp;
}

// gather split rows: dst[row] = src[ids[row]]
__global__ void gather_split_kernel(const uint2* __restrict__ srch, const uint2* __restrict__ srcl,
                                    const int* __restrict__ ids,
                                    uint2* __restrict__ dsth, uint2* __restrict__ dstl, int rows) {
    int row = blockIdx.x * blockDim.y + threadIdx.y;
    if (row >= rows) return;
    int id = ids[row];
    int x = threadIdx.x;  // 0..63 (uint2 = 4 halves; 64*4 = 256)
    dsth[(size_t)row * 64 + x] = srch[(size_t)id * 64 + x];
    dstl[(size_t)row * 64 + x] = srcl[(size_t)id * 64 + x];
}

// text fp32 -> split fp16 into cat1 @col 256 and cat3 @col 0
__global__ void textconv_kernel(const float4* __restrict__ text,
                                __half* __restrict__ c1h, __half* __restrict__ c1l,
                                __half* __restrict__ c3h, __half* __restrict__ c3l,
                                int rows) {
    int idx = blockIdx.x * blockDim.x + threadIdx.x;
    if (idx >= rows * PLM4) return;
    int row = idx / PLM4;
    int c   = idx - row * PLM4;
    uint2 hp, lp;
    split4h(text[idx], hp, lp);
    *(uint2*)(c1h + (size_t)row * CAT1 + GG + 4 * c) = hp;
    *(uint2*)(c1l + (size_t)row * CAT1 + GG + 4 * c) = lp;
    *(uint2*)(c3h + (size_t)row * CAT3 + 4 * c) = hp;
    *(uint2*)(c3l + (size_t)row * CAT3 + 4 * c) = lp;
}

// weight [K,N] fp32 -> transposed [N,K] hi/lo fp16 (tiled transpose)
__global__ void wconv_kernel(const float* __restrict__ W,
                             __half* __restrict__ Wh, __half* __restrict__ Wl,
                             int Kd, int Nd) {
    __shared__ float t[32][33];
    int kb = blockIdx.y * 32, nb = blockIdx.x * 32;
#pragma unroll
    for (int j = 0; j < 32; j += 8) {
        int k = kb + threadIdx.y + j, n = nb + threadIdx.x;
        t[threadIdx.y + j][threadIdx.x] = W[(size_t)k * Nd + n];
    }
    __syncthreads();
#pragma unroll
    for (int j = 0; j < 32; j += 8) {
        int n = nb + threadIdx.y + j, k = kb + threadIdx.x;
        float x = t[threadIdx.x][threadIdx.y + j];
        __half h = __float2half_rn(x);
        Wh[(size_t)n * Kd + k] = h;
        Wl[(size_t)n * Kd + k] = __float2half_rn(x - __half2float(h));
    }
}

// ---------------- legacy-MMA split-fp16 GEMM ----------------
// D[M,N] = A @ B^T + bias. NPASS=3: ah*bh + ah*bl + al*bh (err ~2^-23);
// NPASS=2: ah*bh + ah*bl (err ~2^-11, used for fc3 only).
// A: [M,K] fp16 hi/lo K-major, B: [N,K] fp16 hi/lo K-major.
// 128x128 CTA tile, BK=32, 8 warps (4m x 2n), cp.async double-buffered,
// ldmatrix fragments, mma.m16n8k16.f16. N%128==0, K%32==0; M arbitrary.
#define RS     80                    // padded smem row stride (bytes) for 64B payload
#define TILEB  (128 * RS)            // 10240 per tile
#define SOFF(b, t) (((b) * 4 + (t)) * TILEB)
#define GEMM_SMEM (8 * TILEB)        // 81920

template <int NPASS>
__global__ __launch_bounds__(256, 1)
void mgemm_kernel(const __half* __restrict__ Ah, const __half* __restrict__ Al,
                  const __half* __restrict__ Bh, const __half* __restrict__ Bl,
                  const float* __restrict__ bias,
                  float* __restrict__ Cf, __half* __restrict__ Ch, __half* __restrict__ Cl,
                  int ldc, int M, int N, int K, int dorelu) {
    extern __shared__ char smem[];
    const uint32_t sb = smem_u32(smem);
    const int tid = threadIdx.x, lane = tid & 31, wid = tid >> 5;
    const int wm = wid & 3, wn = wid >> 2;
    const int bm = blockIdx.y * 128, bn = blockIdx.x * 128;
    const int g = lane >> 2, tg = lane & 3;

    const int srow = tid >> 1;
    const int sc   = (tid & 1) * 2;
    const int arow = bm + srow;
    const bool aok = arow < M;
    const int arA  = aok ? arow : 0;
    const uint32_t asz = aok ? 16u : 0u;
    const int brow = bn + srow;
    const uint32_t doff = srow * RS + sc * 16;

    auto stage = [&](int kt, int b) {
        const size_t ko = (size_t)kt * 32 + sc * 8;
        const __half* pAh = Ah + (size_t)arA * K + ko;
        const __half* pBh = Bh + (size_t)brow * K + ko;
        const __half* pBl = Bl + (size_t)brow * K + ko;
        cp16(sb + SOFF(b, 0) + doff,      pAh,     asz);
        cp16(sb + SOFF(b, 0) + doff + 16, pAh + 8, asz);
        if (NPASS == 3) {
            const __half* pAl = Al + (size_t)arA * K + ko;
            cp16(sb + SOFF(b, 1) + doff,      pAl,     asz);
            cp16(sb + SOFF(b, 1) + doff + 16, pAl + 8, asz);
        }
        cp16(sb + SOFF(b, 2) + doff,      pBh,     16u);
        cp16(sb + SOFF(b, 2) + doff + 16, pBh + 8, 16u);
        cp16(sb + SOFF(b, 3) + doff,      pBl,     16u);
        cp16(sb + SOFF(b, 3) + doff + 16, pBl + 8, 16u);
    };

    const uint32_t aro = (wm * 32 + (lane & 7) + ((lane >> 3) & 1) * 8) * RS;
    const uint32_t ako = ((lane >> 4) & 1) * 16;
    const uint32_t bro = (wn * 64 + (lane & 7) + ((lane >> 4) & 1) * 8) * RS;
    const uint32_t bko = ((lane >> 3) & 1) * 16;

    float acc[2][8][4];
#pragma unroll
    for (int i = 0; i < 2; i++)
#pragma unroll
        for (int j = 0; j < 8; j++)
#pragma unroll
            for (int q = 0; q < 4; q++) acc[i][j][q] = 0.f;

    const int nk = K >> 5;
    stage(0, 0);
    CP_COMMIT();

    for (int t = 0; t < nk; t++) {
        const int b = t & 1;
        if (t + 1 < nk) {
            stage(t + 1, b ^ 1);
            CP_COMMIT();
            CP_WAIT(1);
        } else {
            CP_WAIT(0);
        }
        __syncthreads();

        const uint32_t baseAH = sb + SOFF(b, 0);
        const uint32_t baseAL = sb + SOFF(b, 1);
        const uint32_t baseBH = sb + SOFF(b, 2);
        const uint32_t baseBL = sb + SOFF(b, 3);

#pragma unroll
        for (int s = 0; s < 2; s++) {
            const uint32_t kb = s * 32;
            uint32_t ah[2][4], al[2][4], bh[8][2], bl[8][2];
#pragma unroll
            for (int mt = 0; mt < 2; mt++) {
                ldsm4(ah[mt], baseAH + aro + mt * (16 * RS) + kb + ako);
                if (NPASS == 3)
                    ldsm4(al[mt], baseAL + aro + mt * (16 * RS) + kb + ako);
            }
#pragma unroll
            for (int p = 0; p < 4; p++) {
                uint32_t r[4];
                ldsm4(r, baseBH + bro + p * (16 * RS) + kb + bko);
                bh[2 * p][0] = r[0]; bh[2 * p][1] = r[1];
                bh[2 * p + 1][0] = r[2]; bh[2 * p + 1][1] = r[3];
                ldsm4(r, baseBL + bro + p * (16 * RS) + kb + bko);
                bl[2 * p][0] = r[0]; bl[2 * p][1] = r[1];
                bl[2 * p + 1][0] = r[2]; bl[2 * p + 1][1] = r[3];
            }
#pragma unroll
            for (int nt = 0; nt < 8; nt++)
#pragma unroll
                for (int mt = 0; mt < 2; mt++) {
                    mma16816(acc[mt][nt], ah[mt], bh[nt][0], bh[nt][1]);   // hi*hi
                    mma16816(acc[mt][nt], ah[mt], bl[nt][0], bl[nt][1]);   // hi*lo
                    if (NPASS == 3)
                        mma16816(acc[mt][nt], al[mt], bh[nt][0], bh[nt][1]); // lo*hi
                }
        }
        __syncthreads();
    }

    // ---- epilogue ----
#pragma unroll
    for (int nt = 0; nt < 8; nt++) {
        const int col = bn + wn * 64 + nt * 8 + 2 * tg;
        float2 bv = *(const float2*)&bias[col];
#pragma unroll
        for (int mt = 0; mt < 2; mt++) {
            const int row0 = bm + wm * 32 + mt * 16 + g;
            float v0 = acc[mt][nt][0] + bv.x;
            float v1 = acc[mt][nt][1] + bv.y;
            float v2 = acc[mt][nt][2] + bv.x;
            float v3 = acc[mt][nt][3] + bv.y;
            if (dorelu) {
                v0 = fmaxf(v0, 0.f); v1 = fmaxf(v1, 0.f);
                v2 = fmaxf(v2, 0.f); v3 = fmaxf(v3, 0.f);
            }
            if (Ch) {
                if (row0 < M) {
                    __half h0 = __float2half_rn(v0), h1 = __float2half_rn(v1);
                    *(uint32_t*)(Ch + (size_t)row0 * ldc + col) =
                        ((uint32_t)__half_as_ushort(h1) << 16) | (uint32_t)__half_as_ushort(h0);
                    *(uint32_t*)(Cl + (size_t)row0 * ldc + col) =
                        packh(v0 - __half2float(h0), v1 - __half2float(h1));
                }
                if (row0 + 8 < M) {
                    __half h2 = __float2half_rn(v2), h3 = __float2half_rn(v3);
                    *(uint32_t*)(Ch + (size_t)(row0 + 8) * ldc + col) =
                        ((uint32_t)__half_as_ushort(h3) << 16) | (uint32_t)__half_as_ushort(h2);
                    *(uint32_t*)(Cl + (size_t)(row0 + 8) * ldc + col) =
                        packh(v2 - __half2float(h2), v3 - __half2float(h3));
                }
            } else {
                if (row0 < M)
                    *(float2*)&Cf[(size_t)row0 * ldc + col] = make_float2(v0, v1);
                if (row0 + 8 < M)
                    *(float2*)&Cf[(size_t)(row0 + 8) * ldc + col] = make_float2(v2, v3);
            }
        }
    }
}

// ---------------- host launcher ----------------
template <int NPASS>
static void mgemm(const __half* Ah, const __half* Al, const __half* Bh, const __half* Bl,
                  const float* bias, float* Cf, __half* Ch, __half* Cl,
                  int ldc, int M, int N, int K) {
    dim3 grid(N / 128, (M + 127) / 128);
    mgemm_kernel<NPASS><<<grid, 256, GEMM_SMEM>>>(Ah, Al, Bh, Bl, bias, Cf, Ch, Cl,
                                                  ldc, M, N, K, 0);
}

extern "C" void kernel_launch(void* const* d_in, const int* in_sizes, int n_in,
                              void* d_out, int out_size) {
    (void)in_sizes; (void)n_in; (void)out_size;

    const float* text   = (const float*)d_in[0];
    const float* wm_x   = (const float*)d_in[1];
    const int*   wm_ei  = (const int*)  d_in[2];
    const int*   t2n    = (const int*)  d_in[3];
    const int*   fids   = (const int*)  d_in[4];
    const int*   f_ei   = (const int*)  d_in[5];
    // d_in[6] extra_emb: unreachable (indices always >= 2)
    const float* wm_W1  = (const float*)d_in[7];
    const float* wm_b1  = (const float*)d_in[8];
    const float* wm_W2  = (const float*)d_in[9];
    const float* wm_b2  = (const float*)d_in[10];
    const float* f_W1   = (const float*)d_in[11];
    const float* f_b1   = (const float*)d_in[12];
    const float* f_W2   = (const float*)d_in[13];
    const float* f_b2   = (const float*)d_in[14];
    const float* fc1_W  = (const float*)d_in[15];
    const float* fc1_b  = (const float*)d_in[16];
    const float* fc3_W  = (const float*)d_in[17];
    const float* fc3_b  = (const float*)d_in[18];
    float* out = (float*)d_out;

    cudaFuncSetAttribute(mgemm_kernel<3>, cudaFuncAttributeMaxDynamicSharedMemorySize, GEMM_SMEM);
    cudaFuncSetAttribute(mgemm_kernel<2>, cudaFuncAttributeMaxDynamicSharedMemorySize, GEMM_SMEM);

    float *bufH, *bufG, *fM, *fH, *zb;
    __half *ah, *al, *gteh, *gtel, *c1h, *c1l, *c3h, *c3l;
    __half *w1h, *w1l, *w2h, *w2l, *gh1, *gl1, *gh2, *gl2, *p1h, *p1l, *p3h, *p3l;
    int *wrp, *wcur, *wcol, *frp, *fcur, *fcol;
    cudaGetSymbolAddress((void**)&bufH, g_bufH);
    cudaGetSymbolAddress((void**)&bufG, g_bufG);
    cudaGetSymbolAddress((void**)&fM,   g_fM);
    cudaGetSymbolAddress((void**)&fH,   g_fH);
    cudaGetSymbolAddress((void**)&zb,   g_zerob);
    cudaGetSymbolAddress((void**)&ah,   g_ah);
    cudaGetSymbolAddress((void**)&al,   g_al);
    cudaGetSymbolAddress((void**)&gteh, g_gteh);
    cudaGetSymbolAddress((void**)&gtel, g_gtel);
    cudaGetSymbolAddress((void**)&c1h,  g_c1h);
    cudaGetSymbolAddress((void**)&c1l,  g_c1l);
    cudaGetSymbolAddress((void**)&c3h,  g_c3h);
    cudaGetSymbolAddress((void**)&c3l,  g_c3l);
    cudaGetSymbolAddress((void**)&w1h,  g_w1h);
    cudaGetSymbolAddress((void**)&w1l,  g_w1l);
    cudaGetSymbolAddress((void**)&w2h,  g_w2h);
    cudaGetSymbolAddress((void**)&w2l,  g_w2l);
    cudaGetSymbolAddress((void**)&gh1,  g_g1h);
    cudaGetSymbolAddress((void**)&gl1,  g_g1l);
    cudaGetSymbolAddress((void**)&gh2,  g_g2h);
    cudaGetSymbolAddress((void**)&gl2,  g_g2l);
    cudaGetSymbolAddress((void**)&p1h,  g_fc1h);
    cudaGetSymbolAddress((void**)&p1l,  g_fc1l);
    cudaGetSymbolAddress((void**)&p3h,  g_fc3h);
    cudaGetSymbolAddress((void**)&p3l,  g_fc3l);
    cudaGetSymbolAddress((void**)&wrp,  g_wm_rowptr);
    cudaGetSymbolAddress((void**)&wcur, g_wm_cur);
    cudaGetSymbolAddress((void**)&wcol, g_wm_col);
    cudaGetSymbolAddress((void**)&frp,  g_f_rowptr);
    cudaGetSymbolAddress((void**)&fcur, g_f_cur);
    cudaGetSymbolAddress((void**)&fcol, g_f_col);

    const dim3 bSp(64, 4);
    const dim3 wcb(32, 8);

    // ===== WM layer 1 (GEMM first via linearity; ncu -s 5 captures launch #6 = GEMM) =====
    split_x_kernel<<<(NWM * G4 + 255) / 256, 256>>>((const float4*)wm_x, ah, al, NWM * G4); // 1
    wconv_kernel<<<dim3(GG / 32, GG / 32), wcb>>>(wm_W1, w1h, w1l, GG, GG);                 // 2
    zero_int_kernel<<<(NWM + 255) / 256, 256>>>(wcur, NWM);                                 // 3
    hist_kernel<<<(EWM + 255) / 256, 256>>>(wm_ei + EWM, wcur, EWM);                        // 4
    scan_kernel<<<1, 1024>>>(wcur, wrp, NWM, EWM);                                          // 5
    mgemm<3>(ah, al, w1h, w1l, zb, bufH, nullptr, nullptr, GG, NWM, GG, GG);                // 6 <- ncu
    fill_kernel<<<(EWM + 255) / 256, 256>>>(wm_ei, wm_ei + EWM, wcur, wcol, EWM);           // 7
    spmm_post_split_kernel<<<(NWM + 3) / 4, bSp>>>((const float4*)bufH, wrp, wcol, wm_b1,
                                                   ah, al, GG, 0, NWM);                     // 8
    // ===== WM layer 2 =====
    wconv_kernel<<<dim3(GG / 32, GG / 32), wcb>>>(wm_W2, w2h, w2l, GG, GG);
    mgemm<3>(ah, al, w2h, w2l, zb, bufH, nullptr, nullptr, GG, NWM, GG, GG);
    spmm_post_f32_kernel<<<(NWM + 3) / 4, bSp>>>((const float4*)bufH, wrp, wcol, wm_b2,
                                                 (float4*)bufG, NWM);
    // bufG = graph_embeddings [NWM, G] fp32

    // ===== token concept sum + text conversion -> cat buffers =====
    gather4sum_split_kernel<<<(NF + 3) / 4, bSp>>>((const float4*)bufG, t2n,
                                                   c1h, c1l, c3h, c3l, NF);
    textconv_kernel<<<(NF * PLM4 + 255) / 256, 256>>>((const float4*)text, c1h, c1l, c3h, c3l, NF);

    // ===== fc1 (split output) =====
    wconv_kernel<<<dim3(GG / 32, CAT1 / 32), wcb>>>(fc1_W, p1h, p1l, CAT1, GG);
    mgemm<3>(c1h, c1l, p1h, p1l, fc1_b, nullptr, gteh, gtel, GG, NF, GG, CAT1);

    // ===== FSTM CSR + gather =====
    zero_int_kernel<<<(NF + 255) / 256, 256>>>(fcur, NF);
    hist_kernel<<<(EF + 255) / 256, 256>>>(f_ei + EF, fcur, EF);
    scan_kernel<<<1, 1024>>>(fcur, frp, NF, EF);
    fill_kernel<<<(EF + 255) / 256, 256>>>(f_ei, f_ei + EF, fcur, fcol, EF);
    gather_split_kernel<<<(NF + 3) / 4, bSp>>>((const uint2*)gteh, (const uint2*)gtel, fids,
                                               (uint2*)ah, (uint2*)al, NF);

    // ===== FSTM layer 1 =====
    wconv_kernel<<<dim3(GG / 32, GG / 32), wcb>>>(f_W1, gh1, gl1, GG, GG);
    mgemm<3>(ah, al, gh1, gl1, zb, fM, nullptr, nullptr, GG, NF, GG, GG);
    spmm_post_split_kernel<<<(NF + 3) / 4, bSp>>>((const float4*)fM, frp, fcol, f_b1,
                                                  ah, al, GG, 0, NF);
    // ===== FSTM layer 2 (split output straight into cat3 @ col 1024) =====
    wconv_kernel<<<dim3(GG / 32, GG / 32), wcb>>>(f_W2, gh2, gl2, GG, GG);
    mgemm<3>(ah, al, gh2, gl2, zb, fH, nullptr, nullptr, GG, NF, GG, GG);
    spmm_post_split_kernel<<<(NF + 3) / 4, bSp>>>((const float4*)fH, frp, fcol, f_b2,
                                                  c3h, c3l, CAT3, PLM + GG, NF);

    // ===== fc3 -> out (2-pass: biggest GEMM, 1/3 fewer MMAs) =====
    wconv_kernel<<<dim3(PLM / 32, CAT3 / 32), wcb>>>(fc3_W, p3h, p3l, CAT3, PLM);
    mgemm<2>(c3h, c3l, p3h, p3l, fc3_b, out, nullptr, nullptr, PLM, NF, PLM, CAT3);
}

// round 7
// speedup vs baseline: 1.2502x; 1.0968x over previous
#include <cuda_runtime.h>
#include <cuda_fp16.h>
#include <cstdint>

// ---------------- problem constants ----------------
#define PLM   768
#define GG    256
#define NWM   50000
#define EWM   800000
#define NF    16384           // B*S
#define EF    131072
#define KSLOT 4
#define G4    (GG/4)          // 64 float4 per G-row
#define PLM4  (PLM/4)         // 192 float4 per PLM-row
#define CAT3  (PLM + 2*GG)    // 1280
#define CAT1  (GG + PLM)      // 1024

// ---------------- device scratch (no runtime alloc allowed) ----------------
__device__ __align__(16) float g_bufH[(size_t)NWM * GG];   // t = h @ W   (WM, reused)
__device__ __align__(16) float g_bufG[(size_t)NWM * GG];   // graph embeddings (fp32)
__device__ __align__(16) float g_fM  [(size_t)NWM * GG];
__device__ __align__(16) float g_fH  [(size_t)NF * GG];
__device__ __align__(16) float g_zerob[PLM];               // zero bias (BSS)
// fp16 split activation buffers
__device__ __align__(16) __half g_ah [(size_t)NWM * GG];
__device__ __align__(16) __half g_al [(size_t)NWM * GG];
__device__ __align__(16) __half g_gteh[(size_t)NF * GG];
__device__ __align__(16) __half g_gtel[(size_t)NF * GG];
__device__ __align__(16) __half g_c1h[(size_t)NF * CAT1];
__device__ __align__(16) __half g_c1l[(size_t)NF * CAT1];
__device__ __align__(16) __half g_c3h[(size_t)NF * CAT3];   // fc3 is 2-pass: lo plane not needed
// fp16 split transposed weights [N, K]
__device__ __align__(16) __half g_w1h[GG * GG];
__device__ __align__(16) __half g_w1l[GG * GG];
__device__ __align__(16) __half g_w2h[GG * GG];
__device__ __align__(16) __half g_w2l[GG * GG];
__device__ __align__(16) __half g_g1h[GG * GG];
__device__ __align__(16) __half g_g1l[GG * GG];
__device__ __align__(16) __half g_g2h[GG * GG];
__device__ __align__(16) __half g_g2l[GG * GG];
__device__ __align__(16) __half g_fc1h[GG * CAT1];
__device__ __align__(16) __half g_fc1l[GG * CAT1];
__device__ __align__(16) __half g_fc3h[PLM * CAT3];
__device__ __align__(16) __half g_fc3l[PLM * CAT3];
// CSR
__device__ int g_wm_rowptr[NWM + 1];
__device__ int g_wm_cur[NWM];
__device__ int g_wm_col[EWM];
__device__ int g_f_rowptr[NF + 1];
__device__ int g_f_cur[NF];
__device__ int g_f_col[EF];

// ---------------- helpers ----------------
__device__ __forceinline__ uint32_t smem_u32(const void* p) {
    uint32_t a;
    asm("{ .reg .u64 t; cvta.to.shared.u64 t, %1; cvt.u32.u64 %0, t; }" : "=r"(a) : "l"(p));
    return a;
}
__device__ __forceinline__ void cp16(uint32_t dst, const void* src, uint32_t srcsize) {
    asm volatile("cp.async.cg.shared.global [%0], [%1], 16, %2;"
                 :: "r"(dst), "l"(src), "r"(srcsize) : "memory");
}
#define CP_COMMIT() asm volatile("cp.async.commit_group;" ::: "memory")
#define CP_WAIT(n)  asm volatile("cp.async.wait_group %0;" :: "n"(n) : "memory")

__device__ __forceinline__ void ldsm4(uint32_t* r, uint32_t addr) {
    asm volatile("ldmatrix.sync.aligned.m8n8.x4.shared.b16 {%0,%1,%2,%3}, [%4];"
                 : "=r"(r[0]), "=r"(r[1]), "=r"(r[2]), "=r"(r[3]) : "r"(addr));
}
__device__ __forceinline__ void mma16816(float* c, const uint32_t* a, uint32_t b0, uint32_t b1) {
    asm volatile(
        "mma.sync.aligned.m16n8k16.row.col.f32.f16.f16.f32 "
        "{%0,%1,%2,%3}, {%4,%5,%6,%7}, {%8,%9}, {%0,%1,%2,%3};\n"
        : "+f"(c[0]), "+f"(c[1]), "+f"(c[2]), "+f"(c[3])
        : "r"(a[0]), "r"(a[1]), "r"(a[2]), "r"(a[3]), "r"(b0), "r"(b1));
}

__device__ __forceinline__ uint32_t packh(float a, float b) {
    __half ha = __float2half_rn(a), hb = __float2half_rn(b);
    return ((uint32_t)__half_as_ushort(hb) << 16) | (uint32_t)__half_as_ushort(ha);
}
__device__ __forceinline__ void split4h(float4 v, uint2& hp, uint2& lp) {
    __half h0 = __float2half_rn(v.x), h1 = __float2half_rn(v.y);
    __half h2 = __float2half_rn(v.z), h3 = __float2half_rn(v.w);
    hp.x = ((uint32_t)__half_as_ushort(h1) << 16) | (uint32_t)__half_as_ushort(h0);
    hp.y = ((uint32_t)__half_as_ushort(h3) << 16) | (uint32_t)__half_as_ushort(h2);
    lp.x = packh(v.x - __half2float(h0), v.y - __half2float(h1));
    lp.y = packh(v.z - __half2float(h2), v.w - __half2float(h3));
}
__device__ __forceinline__ uint2 pack4h(float4 v) {
    uint2 hp;
    hp.x = packh(v.x, v.y);
    hp.y = packh(v.z, v.w);
    return hp;
}

// ---------------- CSR build kernels ----------------
__global__ void zero_int_kernel(int* __restrict__ p, int n) {
    int i = blockIdx.x * blockDim.x + threadIdx.x;
    if (i < n) p[i] = 0;
}
__global__ void hist_kernel(const int* __restrict__ dst, int* __restrict__ cnt, int E) {
    int e = blockIdx.x * blockDim.x + threadIdx.x;
    if (e < E) atomicAdd(&cnt[dst[e]], 1);
}
__global__ void scan_kernel(int* __restrict__ cnt_cur, int* __restrict__ rowptr, int N, int E) {
    __shared__ int sh[1024];
    int tid = threadIdx.x;
    int chunk = (N + 1023) >> 10;
    int s0 = tid * chunk;
    int s1 = s0 + chunk; if (s1 > N) s1 = N;
    int s = 0;
    for (int i = s0; i < s1; i++) s += cnt_cur[i];
    sh[tid] = s;
    __syncthreads();
    for (int off = 1; off < 1024; off <<= 1) {
        int v = (tid >= off) ? sh[tid - off] : 0;
        __syncthreads();
        sh[tid] += v;
        __syncthreads();
    }
    int run = sh[tid] - s;
    for (int i = s0; i < s1; i++) {
        int c = cnt_cur[i];
        rowptr[i]  = run;
        cnt_cur[i] = run;
        run += c;
    }
    if (tid == 0) rowptr[N] = E;
}
__global__ void fill_kernel(const int* __restrict__ src, const int* __restrict__ dst,
                            int* __restrict__ cur, int* __restrict__ col, int E) {
    int e = blockIdx.x * blockDim.x + threadIdx.x;
    if (e < E) {
        int d = dst[e];
        int p = atomicAdd(&cur[d], 1);
        col[p] = src[e];
    }
}

// ---------------- elementwise / gather kernels ----------------
// fp32 -> fp16 hi only (for 2-pass GEMM inputs)
__global__ void split_x_hi_kernel(const float4* __restrict__ x,
                                  __half* __restrict__ oh, int n4) {
    int idx = blockIdx.x * blockDim.x + threadIdx.x;
    if (idx >= n4) return;
    *(uint2*)(oh + 4 * (size_t)idx) = pack4h(x[idx]);
}

// aggregate post-GEMM: v = relu(t[n] + sum t[src] + bias); write split (ol optional)
__global__ void spmm_post_split_kernel(const float4* __restrict__ t,
                                       const int* __restrict__ rowptr,
                                       const int* __restrict__ col,
                                       const float* __restrict__ bias,
                                       __half* __restrict__ oh, __half* __restrict__ ol,
                                       size_t ldo, size_t coff, int n) {
    int node = blockIdx.x * blockDim.y + threadIdx.y;
    if (node >= n) return;
    int x = threadIdx.x;  // 0..63
    float4 acc = t[(size_t)node * G4 + x];
    int e  = rowptr[node];
    int e1 = rowptr[node + 1];
    for (; e + 4 <= e1; e += 4) {
        int s0 = __ldg(&col[e]), s1 = __ldg(&col[e + 1]);
        int s2 = __ldg(&col[e + 2]), s3 = __ldg(&col[e + 3]);
        float4 v0 = __ldg(&t[(size_t)s0 * G4 + x]);
        float4 v1 = __ldg(&t[(size_t)s1 * G4 + x]);
        float4 v2 = __ldg(&t[(size_t)s2 * G4 + x]);
        float4 v3 = __ldg(&t[(size_t)s3 * G4 + x]);
        acc.x += v0.x + v1.x + v2.x + v3.x;
        acc.y += v0.y + v1.y + v2.y + v3.y;
        acc.z += v0.z + v1.z + v2.z + v3.z;
        acc.w += v0.w + v1.w + v2.w + v3.w;
    }
    for (; e < e1; ++e) {
        int s = __ldg(&col[e]);
        float4 v = __ldg(&t[(size_t)s * G4 + x]);
        acc.x += v.x; acc.y += v.y; acc.z += v.z; acc.w += v.w;
    }
    float4 bv = *(const float4*)&bias[4 * x];
    acc.x = fmaxf(acc.x + bv.x, 0.f);
    acc.y = fmaxf(acc.y + bv.y, 0.f);
    acc.z = fmaxf(acc.z + bv.z, 0.f);
    acc.w = fmaxf(acc.w + bv.w, 0.f);
    if (ol) {
        uint2 hp, lp;
        split4h(acc, hp, lp);
        *(uint2*)(oh + (size_t)node * ldo + coff + 4 * x) = hp;
        *(uint2*)(ol + (size_t)node * ldo + coff + 4 * x) = lp;
    } else {
        *(uint2*)(oh + (size_t)node * ldo + coff + 4 * x) = pack4h(acc);
    }
}

// aggregate post-GEMM, fp32 output
__global__ void spmm_post_f32_kernel(const float4* __restrict__ t,
                                     const int* __restrict__ rowptr,
                                     const int* __restrict__ col,
                                     const float* __restrict__ bias,
                                     float4* __restrict__ out, int n) {
    int node = blockIdx.x * blockDim.y + threadIdx.y;
    if (node >= n) return;
    int x = threadIdx.x;
    float4 acc = t[(size_t)node * G4 + x];
    int e  = rowptr[node];
    int e1 = rowptr[node + 1];
    for (; e + 4 <= e1; e += 4) {
        int s0 = __ldg(&col[e]), s1 = __ldg(&col[e + 1]);
        int s2 = __ldg(&col[e + 2]), s3 = __ldg(&col[e + 3]);
        float4 v0 = __ldg(&t[(size_t)s0 * G4 + x]);
        float4 v1 = __ldg(&t[(size_t)s1 * G4 + x]);
        float4 v2 = __ldg(&t[(size_t)s2 * G4 + x]);
        float4 v3 = __ldg(&t[(size_t)s3 * G4 + x]);
        acc.x += v0.x + v1.x + v2.x + v3.x;
        acc.y += v0.y + v1.y + v2.y + v3.y;
        acc.z += v0.z + v1.z + v2.z + v3.z;
        acc.w += v0.w + v1.w + v2.w + v3.w;
    }
    for (; e < e1; ++e) {
        int s = __ldg(&col[e]);
        float4 v = __ldg(&t[(size_t)s * G4 + x]);
        acc.x += v.x; acc.y += v.y; acc.z += v.z; acc.w += v.w;
    }
    float4 bv = *(const float4*)&bias[4 * x];
    acc.x = fmaxf(acc.x + bv.x, 0.f);
    acc.y = fmaxf(acc.y + bv.y, 0.f);
    acc.z = fmaxf(acc.z + bv.z, 0.f);
    acc.w = fmaxf(acc.w + bv.w, 0.f);
    out[(size_t)node * G4 + x] = acc;
}

// tmp[row] = sum_k ge[t2n[row*4+k]]; split into cat1 @col0; hi-only into cat3 @col768
__global__ void gather4sum_split_kernel(const float4* __restrict__ ge,
                                        const int* __restrict__ t2n,
                                        __half* __restrict__ c1h, __half* __restrict__ c1l,
                                        __half* __restrict__ c3h, int rows) {
    int row = blockIdx.x * blockDim.y + threadIdx.y;
    if (row >= rows) return;
    int x = threadIdx.x;
    float4 acc = make_float4(0.f, 0.f, 0.f, 0.f);
#pragma unroll
    for (int k = 0; k < KSLOT; k++) {
        int idx = __ldg(&t2n[row * KSLOT + k]);
        float4 v = __ldg(&ge[(size_t)idx * G4 + x]);
        acc.x += v.x; acc.y += v.y; acc.z += v.z; acc.w += v.w;
    }
    uint2 hp, lp;
    split4h(acc, hp, lp);
    *(uint2*)(c1h + (size_t)row * CAT1 + 4 * x) = hp;
    *(uint2*)(c1l + (size_t)row * CAT1 + 4 * x) = lp;
    *(uint2*)(c3h + (size_t)row * CAT3 + PLM + 4 * x) = hp;
}

// gather split rows: dst[row] = src[ids[row]]
__global__ void gather_split_kernel(const uint2* __restrict__ srch, const uint2* __restrict__ srcl,
                                    const int* __restrict__ ids,
                                    uint2* __restrict__ dsth, uint2* __restrict__ dstl, int rows) {
    int row = blockIdx.x * blockDim.y + threadIdx.y;
    if (row >= rows) return;
    int id = ids[row];
    int x = threadIdx.x;  // 0..63
    dsth[(size_t)row * 64 + x] = srch[(size_t)id * 64 + x];
    dstl[(size_t)row * 64 + x] = srcl[(size_t)id * 64 + x];
}

// text fp32 -> split into cat1 @col 256; hi-only into cat3 @col 0
__global__ void textconv_kernel(const float4* __restrict__ text,
                                __half* __restrict__ c1h, __half* __restrict__ c1l,
                                __half* __restrict__ c3h, int rows) {
    int idx = blockIdx.x * blockDim.x + threadIdx.x;
    if (idx >= rows * PLM4) return;
    int row = idx / PLM4;
    int c   = idx - row * PLM4;
    uint2 hp, lp;
    split4h(text[idx], hp, lp);
    *(uint2*)(c1h + (size_t)row * CAT1 + GG + 4 * c) = hp;
    *(uint2*)(c1l + (size_t)row * CAT1 + GG + 4 * c) = lp;
    *(uint2*)(c3h + (size_t)row * CAT3 + 4 * c) = hp;
}

// weight [K,N] fp32 -> transposed [N,K] hi/lo fp16
__global__ void wconv_kernel(const float* __restrict__ W,
                             __half* __restrict__ Wh, __half* __restrict__ Wl,
                             int Kd, int Nd) {
    __shared__ float t[32][33];
    int kb = blockIdx.y * 32, nb = blockIdx.x * 32;
#pragma unroll
    for (int j = 0; j < 32; j += 8) {
        int k = kb + threadIdx.y + j, n = nb + threadIdx.x;
        t[threadIdx.y + j][threadIdx.x] = W[(size_t)k * Nd + n];
    }
    __syncthreads();
#pragma unroll
    for (int j = 0; j < 32; j += 8) {
        int n = nb + threadIdx.y + j, k = kb + threadIdx.x;
        float x = t[threadIdx.x][threadIdx.y + j];
        __half h = __float2half_rn(x);
        Wh[(size_t)n * Kd + k] = h;
        Wl[(size_t)n * Kd + k] = __float2half_rn(x - __half2float(h));
    }
}

// ---------------- legacy-MMA split-fp16 GEMM ----------------
// NPASS=3: ah*bh + al*bh + ah*bl (err ~2^-23). NPASS=2: ah*bh + ah*bl (err ~2^-11).
// Tiles per buffer: AH=0, BH=1, BL=2, [AL=3 only NPASS=3].
// NPASS=2 uses 6 tiles smem + 2 CTAs/SM; NPASS=3 uses 8 tiles + 1 CTA/SM.
#define RS     80
#define TILEB  (128 * RS)            // 10240

template <int NPASS>
__global__ __launch_bounds__(256, NPASS == 2 ? 2 : 1)
void mgemm_kernel(const __half* __restrict__ Ah, const __half* __restrict__ Al,
                  const __half* __restrict__ Bh, const __half* __restrict__ Bl,
                  const float* __restrict__ bias,
                  float* __restrict__ Cf, __half* __restrict__ Ch, __half* __restrict__ Cl,
                  int ldc, int M, int N, int K, int dorelu) {
    constexpr int NT = (NPASS == 3) ? 4 : 3;
    extern __shared__ char smem[];
    const uint32_t sb = smem_u32(smem);
    const int tid = threadIdx.x, lane = tid & 31, wid = tid >> 5;
    const int wm = wid & 3, wn = wid >> 2;
    const int bm = blockIdx.y * 128, bn = blockIdx.x * 128;
    const int g = lane >> 2, tg = lane & 3;

    const int srow = tid >> 1;
    const int sc   = (tid & 1) * 2;
    const int arow = bm + srow;
    const bool aok = arow < M;
    const int arA  = aok ? arow : 0;
    const uint32_t asz = aok ? 16u : 0u;
    const int brow = bn + srow;
    const uint32_t doff = srow * RS + sc * 16;

    auto soff = [&](int b, int t) -> uint32_t { return (uint32_t)((b * NT + t) * TILEB); };

    auto stage = [&](int kt, int b) {
        const size_t ko = (size_t)kt * 32 + sc * 8;
        const __half* pAh = Ah + (size_t)arA * K + ko;
        const __half* pBh = Bh + (size_t)brow * K + ko;
        const __half* pBl = Bl + (size_t)brow * K + ko;
        cp16(sb + soff(b, 0) + doff,      pAh,     asz);
        cp16(sb + soff(b, 0) + doff + 16, pAh + 8, asz);
        cp16(sb + soff(b, 1) + doff,      pBh,     16u);
        cp16(sb + soff(b, 1) + doff + 16, pBh + 8, 16u);
        cp16(sb + soff(b, 2) + doff,      pBl,     16u);
        cp16(sb + soff(b, 2) + doff + 16, pBl + 8, 16u);
        if (NPASS == 3) {
            const __half* pAl = Al + (size_t)arA * K + ko;
            cp16(sb + soff(b, 3) + doff,      pAl,     asz);
            cp16(sb + soff(b, 3) + doff + 16, pAl + 8, asz);
        }
    };

    const uint32_t aro = (wm * 32 + (lane & 7) + ((lane >> 3) & 1) * 8) * RS;
    const uint32_t ako = ((lane >> 4) & 1) * 16;
    const uint32_t bro = (wn * 64 + (lane & 7) + ((lane >> 4) & 1) * 8) * RS;
    const uint32_t bko = ((lane >> 3) & 1) * 16;

    float acc[2][8][4];
#pragma unroll
    for (int i = 0; i < 2; i++)
#pragma unroll
        for (int j = 0; j < 8; j++)
#pragma unroll
            for (int q = 0; q < 4; q++) acc[i][j][q] = 0.f;

    const int nk = K >> 5;
    stage(0, 0);
    CP_COMMIT();

    for (int t = 0; t < nk; t++) {
        const int b = t & 1;
        if (t + 1 < nk) {
            stage(t + 1, b ^ 1);
            CP_COMMIT();
            CP_WAIT(1);
        } else {
            CP_WAIT(0);
        }
        __syncthreads();

        const uint32_t baseAH = sb + soff(b, 0);
        const uint32_t baseBH = sb + soff(b, 1);
        const uint32_t baseBL = sb + soff(b, 2);
        const uint32_t baseAL = sb + soff(b, 3);

#pragma unroll
        for (int s = 0; s < 2; s++) {
            const uint32_t kb = s * 32;
            uint32_t ah2[2][4], al2[2][4], bf[8][2];
#pragma unroll
            for (int mt = 0; mt < 2; mt++) {
                ldsm4(ah2[mt], baseAH + aro + mt * (16 * RS) + kb + ako);
                if (NPASS == 3)
                    ldsm4(al2[mt], baseAL + aro + mt * (16 * RS) + kb + ako);
            }
            // ---- B-hi pass(es) ----
#pragma unroll
            for (int p = 0; p < 4; p++) {
                uint32_t r[4];
                ldsm4(r, baseBH + bro + p * (16 * RS) + kb + bko);
                bf[2 * p][0] = r[0]; bf[2 * p][1] = r[1];
                bf[2 * p + 1][0] = r[2]; bf[2 * p + 1][1] = r[3];
            }
#pragma unroll
            for (int nt = 0; nt < 8; nt++)
#pragma unroll
                for (int mt = 0; mt < 2; mt++) {
                    mma16816(acc[mt][nt], ah2[mt], bf[nt][0], bf[nt][1]);   // hi*hi
                    if (NPASS == 3)
                        mma16816(acc[mt][nt], al2[mt], bf[nt][0], bf[nt][1]); // lo*hi
                }
            // ---- B-lo pass ----
#pragma unroll
            for (int p = 0; p < 4; p++) {
                uint32_t r[4];
                ldsm4(r, baseBL + bro + p * (16 * RS) + kb + bko);
                bf[2 * p][0] = r[0]; bf[2 * p][1] = r[1];
                bf[2 * p + 1][0] = r[2]; bf[2 * p + 1][1] = r[3];
            }
#pragma unroll
            for (int nt = 0; nt < 8; nt++)
#pragma unroll
                for (int mt = 0; mt < 2; mt++)
                    mma16816(acc[mt][nt], ah2[mt], bf[nt][0], bf[nt][1]);   // hi*lo
        }
        __syncthreads();
    }

    // ---- epilogue ----
#pragma unroll
    for (int nt = 0; nt < 8; nt++) {
        const int col = bn + wn * 64 + nt * 8 + 2 * tg;
        float2 bv = *(const float2*)&bias[col];
#pragma unroll
        for (int mt = 0; mt < 2; mt++) {
            const int row0 = bm + wm * 32 + mt * 16 + g;
            float v0 = acc[mt][nt][0] + bv.x;
            float v1 = acc[mt][nt][1] + bv.y;
            float v2 = acc[mt][nt][2] + bv.x;
            float v3 = acc[mt][nt][3] + bv.y;
            if (dorelu) {
                v0 = fmaxf(v0, 0.f); v1 = fmaxf(v1, 0.f);
                v2 = fmaxf(v2, 0.f); v3 = fmaxf(v3, 0.f);
            }
            if (Ch) {
                if (row0 < M) {
                    __half h0 = __float2half_rn(v0), h1 = __float2half_rn(v1);
                    *(uint32_t*)(Ch + (size_t)row0 * ldc + col) =
                        ((uint32_t)__half_as_ushort(h1) << 16) | (uint32_t)__half_as_ushort(h0);
                    *(uint32_t*)(Cl + (size_t)row0 * ldc + col) =
                        packh(v0 - __half2float(h0), v1 - __half2float(h1));
                }
                if (row0 + 8 < M) {
                    __half h2 = __float2half_rn(v2), h3 = __float2half_rn(v3);
                    *(uint32_t*)(Ch + (size_t)(row0 + 8) * ldc + col) =
                        ((uint32_t)__half_as_ushort(h3) << 16) | (uint32_t)__half_as_ushort(h2);
                    *(uint32_t*)(Cl + (size_t)(row0 + 8) * ldc + col) =
                        packh(v2 - __half2float(h2), v3 - __half2float(h3));
                }
            } else {
                if (row0 < M)
                    *(float2*)&Cf[(size_t)row0 * ldc + col] = make_float2(v0, v1);
                if (row0 + 8 < M)
                    *(float2*)&Cf[(size_t)(row0 + 8) * ldc + col] = make_float2(v2, v3);
            }
        }
    }
}

// ---------------- host launcher ----------------
template <int NPASS>
static void mgemm(const __half* Ah, const __half* Al, const __half* Bh, const __half* Bl,
                  const float* bias, float* Cf, __half* Ch, __half* Cl,
                  int ldc, int M, int N, int K) {
    constexpr int smemB = 2 * ((NPASS == 3) ? 4 : 3) * TILEB;
    dim3 grid(N / 128, (M + 127) / 128);
    mgemm_kernel<NPASS><<<grid, 256, smemB>>>(Ah, Al, Bh, Bl, bias, Cf, Ch, Cl,
                                              ldc, M, N, K, 0);
}

extern "C" void kernel_launch(void* const* d_in, const int* in_sizes, int n_in,
                              void* d_out, int out_size) {
    (void)in_sizes; (void)n_in; (void)out_size;

    const float* text   = (const float*)d_in[0];
    const float* wm_x   = (const float*)d_in[1];
    const int*   wm_ei  = (const int*)  d_in[2];
    const int*   t2n    = (const int*)  d_in[3];
    const int*   fids   = (const int*)  d_in[4];
    const int*   f_ei   = (const int*)  d_in[5];
    // d_in[6] extra_emb: unreachable (indices always >= 2)
    const float* wm_W1  = (const float*)d_in[7];
    const float* wm_b1  = (const float*)d_in[8];
    const float* wm_W2  = (const float*)d_in[9];
    const float* wm_b2  = (const float*)d_in[10];
    const float* f_W1   = (const float*)d_in[11];
    const float* f_b1   = (const float*)d_in[12];
    const float* f_W2   = (const float*)d_in[13];
    const float* f_b2   = (const float*)d_in[14];
    const float* fc1_W  = (const float*)d_in[15];
    const float* fc1_b  = (const float*)d_in[16];
    const float* fc3_W  = (const float*)d_in[17];
    const float* fc3_b  = (const float*)d_in[18];
    float* out = (float*)d_out;

    cudaFuncSetAttribute(mgemm_kernel<3>, cudaFuncAttributeMaxDynamicSharedMemorySize, 8 * TILEB);
    cudaFuncSetAttribute(mgemm_kernel<2>, cudaFuncAttributeMaxDynamicSharedMemorySize, 6 * TILEB);

    float *bufH, *bufG, *fM, *fH, *zb;
    __half *ah, *al, *gteh, *gtel, *c1h, *c1l, *c3h;
    __half *w1h, *w1l, *w2h, *w2l, *gh1, *gl1, *gh2, *gl2, *p1h, *p1l, *p3h, *p3l;
    int *wrp, *wcur, *wcol, *frp, *fcur, *fcol;
    cudaGetSymbolAddress((void**)&bufH, g_bufH);
    cudaGetSymbolAddress((void**)&bufG, g_bufG);
    cudaGetSymbolAddress((void**)&fM,   g_fM);
    cudaGetSymbolAddress((void**)&fH,   g_fH);
    cudaGetSymbolAddress((void**)&zb,   g_zerob);
    cudaGetSymbolAddress((void**)&ah,   g_ah);
    cudaGetSymbolAddress((void**)&al,   g_al);
    cudaGetSymbolAddress((void**)&gteh, g_gteh);
    cudaGetSymbolAddress((void**)&gtel, g_gtel);
    cudaGetSymbolAddress((void**)&c1h,  g_c1h);
    cudaGetSymbolAddress((void**)&c1l,  g_c1l);
    cudaGetSymbolAddress((void**)&c3h,  g_c3h);
    cudaGetSymbolAddress((void**)&w1h,  g_w1h);
    cudaGetSymbolAddress((void**)&w1l,  g_w1l);
    cudaGetSymbolAddress((void**)&w2h,  g_w2h);
    cudaGetSymbolAddress((void**)&w2l,  g_w2l);
    cudaGetSymbolAddress((void**)&gh1,  g_g1h);
    cudaGetSymbolAddress((void**)&gl1,  g_g1l);
    cudaGetSymbolAddress((void**)&gh2,  g_g2h);
    cudaGetSymbolAddress((void**)&gl2,  g_g2l);
    cudaGetSymbolAddress((void**)&p1h,  g_fc1h);
    cudaGetSymbolAddress((void**)&p1l,  g_fc1l);
    cudaGetSymbolAddress((void**)&p3h,  g_fc3h);
    cudaGetSymbolAddress((void**)&p3l,  g_fc3l);
    cudaGetSymbolAddress((void**)&wrp,  g_wm_rowptr);
    cudaGetSymbolAddress((void**)&wcur, g_wm_cur);
    cudaGetSymbolAddress((void**)&wcol, g_wm_col);
    cudaGetSymbolAddress((void**)&frp,  g_f_rowptr);
    cudaGetSymbolAddress((void**)&fcur, g_f_cur);
    cudaGetSymbolAddress((void**)&fcol, g_f_col);

    const dim3 bSp(64, 4);
    const dim3 wcb(32, 8);

    // ===== WM layer 1 (2-pass: A-hi only; GEMM is launch #6 for ncu) =====
    split_x_hi_kernel<<<(NWM * G4 + 255) / 256, 256>>>((const float4*)wm_x, ah, NWM * G4); // 1
    wconv_kernel<<<dim3(GG / 32, GG / 32), wcb>>>(wm_W1, w1h, w1l, GG, GG);                // 2
    zero_int_kernel<<<(NWM + 255) / 256, 256>>>(wcur, NWM);                                // 3
    hist_kernel<<<(EWM + 255) / 256, 256>>>(wm_ei + EWM, wcur, EWM);                       // 4
    scan_kernel<<<1, 1024>>>(wcur, wrp, NWM, EWM);                                         // 5
    mgemm<2>(ah, ah, w1h, w1l, zb, bufH, nullptr, nullptr, GG, NWM, GG, GG);               // 6 <- ncu
    fill_kernel<<<(EWM + 255) / 256, 256>>>(wm_ei, wm_ei + EWM, wcur, wcol, EWM);          // 7
    spmm_post_split_kernel<<<(NWM + 3) / 4, bSp>>>((const float4*)bufH, wrp, wcol, wm_b1,
                                                   ah, nullptr, GG, 0, NWM);               // 8
    // ===== WM layer 2 (2-pass) =====
    wconv_kernel<<<dim3(GG / 32, GG / 32), wcb>>>(wm_W2, w2h, w2l, GG, GG);
    mgemm<2>(ah, ah, w2h, w2l, zb, bufH, nullptr, nullptr, GG, NWM, GG, GG);
    spmm_post_f32_kernel<<<(NWM + 3) / 4, bSp>>>((const float4*)bufH, wrp, wcol, wm_b2,
                                                 (float4*)bufG, NWM);
    // bufG = graph_embeddings [NWM, G] fp32

    // ===== token concept sum + text conversion -> cat buffers =====
    gather4sum_split_kernel<<<(NF + 3) / 4, bSp>>>((const float4*)bufG, t2n,
                                                   c1h, c1l, c3h, NF);
    textconv_kernel<<<(NF * PLM4 + 255) / 256, 256>>>((const float4*)text, c1h, c1l, c3h, NF);

    // ===== fc1 (3-pass, split output) =====
    wconv_kernel<<<dim3(GG / 32, CAT1 / 32), wcb>>>(fc1_W, p1h, p1l, CAT1, GG);
    mgemm<3>(c1h, c1l, p1h, p1l, fc1_b, nullptr, gteh, gtel, GG, NF, GG, CAT1);

    // ===== FSTM CSR + gather =====
    zero_int_kernel<<<(NF + 255) / 256, 256>>>(fcur, NF);
    hist_kernel<<<(EF + 255) / 256, 256>>>(f_ei + EF, fcur, EF);
    scan_kernel<<<1, 1024>>>(fcur, frp, NF, EF);
    fill_kernel<<<(EF + 255) / 256, 256>>>(f_ei, f_ei + EF, fcur, fcol, EF);
    gather_split_kernel<<<(NF + 3) / 4, bSp>>>((const uint2*)gteh, (const uint2*)gtel, fids,
                                               (uint2*)ah, (uint2*)al, NF);

    // ===== FSTM layer 1 (3-pass) =====
    wconv_kernel<<<dim3(GG / 32, GG / 32), wcb>>>(f_W1, gh1, gl1, GG, GG);
    mgemm<3>(ah, al, gh1, gl1, zb, fM, nullptr, nullptr, GG, NF, GG, GG);
    spmm_post_split_kernel<<<(NF + 3) / 4, bSp>>>((const float4*)fM, frp, fcol, f_b1,
                                                  ah, al, GG, 0, NF);
    // ===== FSTM layer 2 (3-pass; hi-only output straight into cat3 @ col 1024) =====
    wconv_kernel<<<dim3(GG / 32, GG / 32), wcb>>>(f_W2, gh2, gl2, GG, GG);
    mgemm<3>(ah, al, gh2, gl2, zb, fH, nullptr, nullptr, GG, NF, GG, GG);
    spmm_post_split_kernel<<<(NF + 3) / 4, bSp>>>((const float4*)fH, frp, fcol, f_b2,
                                                  c3h, nullptr, CAT3, PLM + GG, NF);

    // ===== fc3 -> out (2-pass) =====
    wconv_kernel<<<dim3(PLM / 32, CAT3 / 32), wcb>>>(fc3_W, p3h, p3l, CAT3, PLM);
    mgemm<2>(c3h, c3h, p3h, p3l, fc3_b, out, nullptr, nullptr, PLM, NF, PLM, CAT3);
}

// round 8
// speedup vs baseline: 1.4903x; 1.1921x over previous
#include <cuda_runtime.h>
#include <cuda_fp16.h>
#include <cstdint>

// ---------------- problem constants ----------------
#define PLM   768
#define GG    256
#define NWM   50000
#define EWM   800000
#define NF    16384           // B*S
#define EF    131072
#define KSLOT 4
#define G4    (GG/4)          // 64 float4 per G-row
#define PLM4  (PLM/4)         // 192 float4 per PLM-row
#define CAT3  (PLM + 2*GG)    // 1280
#define CAT1  (GG + PLM)      // 1024

// ---------------- device scratch (no runtime alloc allowed) ----------------
__device__ __align__(16) float g_fM  [(size_t)NF * GG];    // fstm t (fp32)
__device__ __align__(16) float g_fH  [(size_t)NF * GG];
__device__ __align__(16) float g_zerob[PLM];               // zero bias (BSS)
// fp16 buffers
__device__ __align__(16) __half g_th [(size_t)NWM * GG];   // WM t (fp16)
__device__ __align__(16) __half g_geh[(size_t)NWM * GG];   // graph embeddings (fp16)
__device__ __align__(16) __half g_ah [(size_t)NWM * GG];   // activations hi
__device__ __align__(16) __half g_al [(size_t)NF * GG];    // activations lo (fstm only)
__device__ __align__(16) __half g_gteh[(size_t)NF * GG];
__device__ __align__(16) __half g_gtel[(size_t)NF * GG];
__device__ __align__(16) __half g_c1h[(size_t)NF * CAT1];
__device__ __align__(16) __half g_c1l[(size_t)NF * CAT1];
__device__ __align__(16) __half g_c3h[(size_t)NF * CAT3];   // fc3 1-pass: lo planes not needed
// fp16 split transposed weights [N, K]
__device__ __align__(16) __half g_w1h[GG * GG];
__device__ __align__(16) __half g_w1l[GG * GG];
__device__ __align__(16) __half g_w2h[GG * GG];
__device__ __align__(16) __half g_w2l[GG * GG];
__device__ __align__(16) __half g_g1h[GG * GG];
__device__ __align__(16) __half g_g1l[GG * GG];
__device__ __align__(16) __half g_g2h[GG * GG];
__device__ __align__(16) __half g_g2l[GG * GG];
__device__ __align__(16) __half g_fc1h[GG * CAT1];
__device__ __align__(16) __half g_fc1l[GG * CAT1];
__device__ __align__(16) __half g_fc3h[PLM * CAT3];
__device__ __align__(16) __half g_fc3l[PLM * CAT3];
// CSR
__device__ int g_wm_rowptr[NWM + 1];
__device__ int g_wm_cur[NWM];
__device__ int g_wm_col[EWM];
__device__ int g_f_rowptr[NF + 1];
__device__ int g_f_cur[NF];
__device__ int g_f_col[EF];

// ---------------- helpers ----------------
__device__ __forceinline__ uint32_t smem_u32(const void* p) {
    uint32_t a;
    asm("{ .reg .u64 t; cvta.to.shared.u64 t, %1; cvt.u32.u64 %0, t; }" : "=r"(a) : "l"(p));
    return a;
}
__device__ __forceinline__ void cp16(uint32_t dst, const void* src, uint32_t srcsize) {
    asm volatile("cp.async.cg.shared.global [%0], [%1], 16, %2;"
                 :: "r"(dst), "l"(src), "r"(srcsize) : "memory");
}
#define CP_COMMIT() asm volatile("cp.async.commit_group;" ::: "memory")
#define CP_WAIT(n)  asm volatile("cp.async.wait_group %0;" :: "n"(n) : "memory")

__device__ __forceinline__ void ldsm4(uint32_t* r, uint32_t addr) {
    asm volatile("ldmatrix.sync.aligned.m8n8.x4.shared.b16 {%0,%1,%2,%3}, [%4];"
                 : "=r"(r[0]), "=r"(r[1]), "=r"(r[2]), "=r"(r[3]) : "r"(addr));
}
__device__ __forceinline__ void mma16816(float* c, const uint32_t* a, uint32_t b0, uint32_t b1) {
    asm volatile(
        "mma.sync.aligned.m16n8k16.row.col.f32.f16.f16.f32 "
        "{%0,%1,%2,%3}, {%4,%5,%6,%7}, {%8,%9}, {%0,%1,%2,%3};\n"
        : "+f"(c[0]), "+f"(c[1]), "+f"(c[2]), "+f"(c[3])
        : "r"(a[0]), "r"(a[1]), "r"(a[2]), "r"(a[3]), "r"(b0), "r"(b1));
}

__device__ __forceinline__ uint32_t packh(float a, float b) {
    __half ha = __float2half_rn(a), hb = __float2half_rn(b);
    return ((uint32_t)__half_as_ushort(hb) << 16) | (uint32_t)__half_as_ushort(ha);
}
__device__ __forceinline__ void split4h(float4 v, uint2& hp, uint2& lp) {
    __half h0 = __float2half_rn(v.x), h1 = __float2half_rn(v.y);
    __half h2 = __float2half_rn(v.z), h3 = __float2half_rn(v.w);
    hp.x = ((uint32_t)__half_as_ushort(h1) << 16) | (uint32_t)__half_as_ushort(h0);
    hp.y = ((uint32_t)__half_as_ushort(h3) << 16) | (uint32_t)__half_as_ushort(h2);
    lp.x = packh(v.x - __half2float(h0), v.y - __half2float(h1));
    lp.y = packh(v.z - __half2float(h2), v.w - __half2float(h3));
}
__device__ __forceinline__ uint2 pack4h(float4 v) {
    uint2 hp;
    hp.x = packh(v.x, v.y);
    hp.y = packh(v.z, v.w);
    return hp;
}
__device__ __forceinline__ float4 h4_to_f4(uint2 u) {
    __half2 a = *(__half2*)&u.x, b = *(__half2*)&u.y;
    float2 fa = __half22float2(a), fb = __half22float2(b);
    return make_float4(fa.x, fa.y, fb.x, fb.y);
}

// ---------------- CSR build kernels ----------------
__global__ void zero_int_kernel(int* __restrict__ p, int n) {
    int i = blockIdx.x * blockDim.x + threadIdx.x;
    if (i < n) p[i] = 0;
}
__global__ void hist_kernel(const int* __restrict__ dst, int* __restrict__ cnt, int E) {
    int e = blockIdx.x * blockDim.x + threadIdx.x;
    if (e < E) atomicAdd(&cnt[dst[e]], 1);
}
__global__ void scan_kernel(int* __restrict__ cnt_cur, int* __restrict__ rowptr, int N, int E) {
    __shared__ int sh[1024];
    int tid = threadIdx.x;
    int chunk = (N + 1023) >> 10;
    int s0 = tid * chunk;
    int s1 = s0 + chunk; if (s1 > N) s1 = N;
    int s = 0;
    for (int i = s0; i < s1; i++) s += cnt_cur[i];
    sh[tid] = s;
    __syncthreads();
    for (int off = 1; off < 1024; off <<= 1) {
        int v = (tid >= off) ? sh[tid - off] : 0;
        __syncthreads();
        sh[tid] += v;
        __syncthreads();
    }
    int run = sh[tid] - s;
    for (int i = s0; i < s1; i++) {
        int c = cnt_cur[i];
        rowptr[i]  = run;
        cnt_cur[i] = run;
        run += c;
    }
    if (tid == 0) rowptr[N] = E;
}
__global__ void fill_kernel(const int* __restrict__ src, const int* __restrict__ dst,
                            int* __restrict__ cur, int* __restrict__ col, int E) {
    int e = blockIdx.x * blockDim.x + threadIdx.x;
    if (e < E) {
        int d = dst[e];
        int p = atomicAdd(&cur[d], 1);
        col[p] = src[e];
    }
}

// ---------------- elementwise / gather kernels ----------------
__global__ void split_x_hi_kernel(const float4* __restrict__ x,
                                  __half* __restrict__ oh, int n4) {
    int idx = blockIdx.x * blockDim.x + threadIdx.x;
    if (idx >= n4) return;
    *(uint2*)(oh + 4 * (size_t)idx) = pack4h(x[idx]);
}

// fp16-t aggregation: v = relu(t[n] + sum t[src] + bias); write fp16 hi-only (strided)
__global__ void spmm_post_h16_kernel(const uint2* __restrict__ t,
                                     const int* __restrict__ rowptr,
                                     const int* __restrict__ col,
                                     const float* __restrict__ bias,
                                     __half* __restrict__ oh,
                                     size_t ldo, size_t coff, int n) {
    int node = blockIdx.x * blockDim.y + threadIdx.y;
    if (node >= n) return;
    int x = threadIdx.x;  // 0..63 (uint2 = 4 halves)
    float4 acc = h4_to_f4(t[(size_t)node * 64 + x]);
    int e  = rowptr[node];
    int e1 = rowptr[node + 1];
    for (; e + 4 <= e1; e += 4) {
        int s0 = __ldg(&col[e]), s1 = __ldg(&col[e + 1]);
        int s2 = __ldg(&col[e + 2]), s3 = __ldg(&col[e + 3]);
        float4 v0 = h4_to_f4(__ldg(&t[(size_t)s0 * 64 + x]));
        float4 v1 = h4_to_f4(__ldg(&t[(size_t)s1 * 64 + x]));
        float4 v2 = h4_to_f4(__ldg(&t[(size_t)s2 * 64 + x]));
        float4 v3 = h4_to_f4(__ldg(&t[(size_t)s3 * 64 + x]));
        acc.x += v0.x + v1.x + v2.x + v3.x;
        acc.y += v0.y + v1.y + v2.y + v3.y;
        acc.z += v0.z + v1.z + v2.z + v3.z;
        acc.w += v0.w + v1.w + v2.w + v3.w;
    }
    for (; e < e1; ++e) {
        int s = __ldg(&col[e]);
        float4 v = h4_to_f4(__ldg(&t[(size_t)s * 64 + x]));
        acc.x += v.x; acc.y += v.y; acc.z += v.z; acc.w += v.w;
    }
    float4 bv = *(const float4*)&bias[4 * x];
    acc.x = fmaxf(acc.x + bv.x, 0.f);
    acc.y = fmaxf(acc.y + bv.y, 0.f);
    acc.z = fmaxf(acc.z + bv.z, 0.f);
    acc.w = fmaxf(acc.w + bv.w, 0.f);
    *(uint2*)(oh + (size_t)node * ldo + coff + 4 * x) = pack4h(acc);
}

// fp32-t aggregation; write split (ol optional)
__global__ void spmm_post_split_kernel(const float4* __restrict__ t,
                                       const int* __restrict__ rowptr,
                                       const int* __restrict__ col,
                                       const float* __restrict__ bias,
                                       __half* __restrict__ oh, __half* __restrict__ ol,
                                       size_t ldo, size_t coff, int n) {
    int node = blockIdx.x * blockDim.y + threadIdx.y;
    if (node >= n) return;
    int x = threadIdx.x;  // 0..63
    float4 acc = t[(size_t)node * G4 + x];
    int e  = rowptr[node];
    int e1 = rowptr[node + 1];
    for (; e + 4 <= e1; e += 4) {
        int s0 = __ldg(&col[e]), s1 = __ldg(&col[e + 1]);
        int s2 = __ldg(&col[e + 2]), s3 = __ldg(&col[e + 3]);
        float4 v0 = __ldg(&t[(size_t)s0 * G4 + x]);
        float4 v1 = __ldg(&t[(size_t)s1 * G4 + x]);
        float4 v2 = __ldg(&t[(size_t)s2 * G4 + x]);
        float4 v3 = __ldg(&t[(size_t)s3 * G4 + x]);
        acc.x += v0.x + v1.x + v2.x + v3.x;
        acc.y += v0.y + v1.y + v2.y + v3.y;
        acc.z += v0.z + v1.z + v2.z + v3.z;
        acc.w += v0.w + v1.w + v2.w + v3.w;
    }
    for (; e < e1; ++e) {
        int s = __ldg(&col[e]);
        float4 v = __ldg(&t[(size_t)s * G4 + x]);
        acc.x += v.x; acc.y += v.y; acc.z += v.z; acc.w += v.w;
    }
    float4 bv = *(const float4*)&bias[4 * x];
    acc.x = fmaxf(acc.x + bv.x, 0.f);
    acc.y = fmaxf(acc.y + bv.y, 0.f);
    acc.z = fmaxf(acc.z + bv.z, 0.f);
    acc.w = fmaxf(acc.w + bv.w, 0.f);
    if (ol) {
        uint2 hp, lp;
        split4h(acc, hp, lp);
        *(uint2*)(oh + (size_t)node * ldo + coff + 4 * x) = hp;
        *(uint2*)(ol + (size_t)node * ldo + coff + 4 * x) = lp;
    } else {
        *(uint2*)(oh + (size_t)node * ldo + coff + 4 * x) = pack4h(acc);
    }
}

// tmp[row] = sum_k ge16[t2n[row*4+k]]; split into cat1 @col0; hi-only into cat3 @col768
__global__ void gather4sum_h_kernel(const uint2* __restrict__ ge,
                                    const int* __restrict__ t2n,
                                    __half* __restrict__ c1h, __half* __restrict__ c1l,
                                    __half* __restrict__ c3h, int rows) {
    int row = blockIdx.x * blockDim.y + threadIdx.y;
    if (row >= rows) return;
    int x = threadIdx.x;
    float4 acc = make_float4(0.f, 0.f, 0.f, 0.f);
#pragma unroll
    for (int k = 0; k < KSLOT; k++) {
        int idx = __ldg(&t2n[row * KSLOT + k]);
        float4 v = h4_to_f4(__ldg(&ge[(size_t)idx * 64 + x]));
        acc.x += v.x; acc.y += v.y; acc.z += v.z; acc.w += v.w;
    }
    uint2 hp, lp;
    split4h(acc, hp, lp);
    *(uint2*)(c1h + (size_t)row * CAT1 + 4 * x) = hp;
    *(uint2*)(c1l + (size_t)row * CAT1 + 4 * x) = lp;
    *(uint2*)(c3h + (size_t)row * CAT3 + PLM + 4 * x) = hp;
}

// gather split rows: dst[row] = src[ids[row]]
__global__ void gather_split_kernel(const uint2* __restrict__ srch, const uint2* __restrict__ srcl,
                                    const int* __restrict__ ids,
                                    uint2* __restrict__ dsth, uint2* __restrict__ dstl, int rows) {
    int row = blockIdx.x * blockDim.y + threadIdx.y;
    if (row >= rows) return;
    int id = ids[row];
    int x = threadIdx.x;  // 0..63
    dsth[(size_t)row * 64 + x] = srch[(size_t)id * 64 + x];
    dstl[(size_t)row * 64 + x] = srcl[(size_t)id * 64 + x];
}

// text fp32 -> split into cat1 @col 256; hi-only into cat3 @col 0
__global__ void textconv_kernel(const float4* __restrict__ text,
                                __half* __restrict__ c1h, __half* __restrict__ c1l,
                                __half* __restrict__ c3h, int rows) {
    int idx = blockIdx.x * blockDim.x + threadIdx.x;
    if (idx >= rows * PLM4) return;
    int row = idx / PLM4;
    int c   = idx - row * PLM4;
    uint2 hp, lp;
    split4h(text[idx], hp, lp);
    *(uint2*)(c1h + (size_t)row * CAT1 + GG + 4 * c) = hp;
    *(uint2*)(c1l + (size_t)row * CAT1 + GG + 4 * c) = lp;
    *(uint2*)(c3h + (size_t)row * CAT3 + 4 * c) = hp;
}

// weight [K,N] fp32 -> transposed [N,K] hi/lo fp16
__global__ void wconv_kernel(const float* __restrict__ W,
                             __half* __restrict__ Wh, __half* __restrict__ Wl,
                             int Kd, int Nd) {
    __shared__ float t[32][33];
    int kb = blockIdx.y * 32, nb = blockIdx.x * 32;
#pragma unroll
    for (int j = 0; j < 32; j += 8) {
        int k = kb + threadIdx.y + j, n = nb + threadIdx.x;
        t[threadIdx.y + j][threadIdx.x] = W[(size_t)k * Nd + n];
    }
    __syncthreads();
#pragma unroll
    for (int j = 0; j < 32; j += 8) {
        int n = nb + threadIdx.y + j, k = kb + threadIdx.x;
        float x = t[threadIdx.x][threadIdx.y + j];
        __half h = __float2half_rn(x);
        Wh[(size_t)n * Kd + k] = h;
        Wl[(size_t)n * Kd + k] = __float2half_rn(x - __half2float(h));
    }
}

// ---------------- legacy-MMA split-fp16 GEMM ----------------
// NPASS=3: ah*bh + al*bh + ah*bl. NPASS=2: ah*bh + ah*bl. NPASS=1: ah*bh.
// Tiles: AH=0, BH=1, [BL=2 if NPASS>=2], [AL=3 if NPASS==3].
#define RS     80
#define TILEB  (128 * RS)            // 10240

template <int NPASS>
__global__ __launch_bounds__(256, 2)
void mgemm_kernel(const __half* __restrict__ Ah, const __half* __restrict__ Al,
                  const __half* __restrict__ Bh, const __half* __restrict__ Bl,
                  const float* __restrict__ bias,
                  float* __restrict__ Cf, __half* __restrict__ Ch, __half* __restrict__ Cl,
                  int ldc, int M, int N, int K, int dorelu) {
    constexpr int NT = (NPASS == 3) ? 4 : ((NPASS == 2) ? 3 : 2);
    extern __shared__ char smem[];
    const uint32_t sb = smem_u32(smem);
    const int tid = threadIdx.x, lane = tid & 31, wid = tid >> 5;
    const int wm = wid & 3, wn = wid >> 2;
    const int bm = blockIdx.y * 128, bn = blockIdx.x * 128;
    const int g = lane >> 2, tg = lane & 3;

    const int srow = tid >> 1;
    const int sc   = (tid & 1) * 2;
    const int arow = bm + srow;
    const bool aok = arow < M;
    const int arA  = aok ? arow : 0;
    const uint32_t asz = aok ? 16u : 0u;
    const int brow = bn + srow;
    const uint32_t doff = srow * RS + sc * 16;

    auto soff = [&](int b, int t) -> uint32_t { return (uint32_t)((b * NT + t) * TILEB); };

    auto stage = [&](int kt, int b) {
        const size_t ko = (size_t)kt * 32 + sc * 8;
        const __half* pAh = Ah + (size_t)arA * K + ko;
        const __half* pBh = Bh + (size_t)brow * K + ko;
        cp16(sb + soff(b, 0) + doff,      pAh,     asz);
        cp16(sb + soff(b, 0) + doff + 16, pAh + 8, asz);
        cp16(sb + soff(b, 1) + doff,      pBh,     16u);
        cp16(sb + soff(b, 1) + doff + 16, pBh + 8, 16u);
        if (NPASS >= 2) {
            const __half* pBl = Bl + (size_t)brow * K + ko;
            cp16(sb + soff(b, 2) + doff,      pBl,     16u);
            cp16(sb + soff(b, 2) + doff + 16, pBl + 8, 16u);
        }
        if (NPASS == 3) {
            const __half* pAl = Al + (size_t)arA * K + ko;
            cp16(sb + soff(b, 3) + doff,      pAl,     asz);
            cp16(sb + soff(b, 3) + doff + 16, pAl + 8, asz);
        }
    };

    const uint32_t aro = (wm * 32 + (lane & 7) + ((lane >> 3) & 1) * 8) * RS;
    const uint32_t ako = ((lane >> 4) & 1) * 16;
    const uint32_t bro = (wn * 64 + (lane & 7) + ((lane >> 4) & 1) * 8) * RS;
    const uint32_t bko = ((lane >> 3) & 1) * 16;

    float acc[2][8][4];
#pragma unroll
    for (int i = 0; i < 2; i++)
#pragma unroll
        for (int j = 0; j < 8; j++)
#pragma unroll
            for (int q = 0; q < 4; q++) acc[i][j][q] = 0.f;

    const int nk = K >> 5;
    stage(0, 0);
    CP_COMMIT();

    for (int t = 0; t < nk; t++) {
        const int b = t & 1;
        if (t + 1 < nk) {
            stage(t + 1, b ^ 1);
            CP_COMMIT();
            CP_WAIT(1);
        } else {
            CP_WAIT(0);
        }
        __syncthreads();

        const uint32_t baseAH = sb + soff(b, 0);
        const uint32_t baseBH = sb + soff(b, 1);
        const uint32_t baseBL = sb + soff(b, 2);
        const uint32_t baseAL = sb + soff(b, 3);

#pragma unroll
        for (int s = 0; s < 2; s++) {
            const uint32_t kb = s * 32;
            uint32_t ah2[2][4], al2[2][4], bf[8][2];
#pragma unroll
            for (int mt = 0; mt < 2; mt++) {
                ldsm4(ah2[mt], baseAH + aro + mt * (16 * RS) + kb + ako);
                if (NPASS == 3)
                    ldsm4(al2[mt], baseAL + aro + mt * (16 * RS) + kb + ako);
            }
            // ---- B-hi pass(es) ----
#pragma unroll
            for (int p = 0; p < 4; p++) {
                uint32_t r[4];
                ldsm4(r, baseBH + bro + p * (16 * RS) + kb + bko);
                bf[2 * p][0] = r[0]; bf[2 * p][1] = r[1];
                bf[2 * p + 1][0] = r[2]; bf[2 * p + 1][1] = r[3];
            }
#pragma unroll
            for (int nt = 0; nt < 8; nt++)
#pragma unroll
                for (int mt = 0; mt < 2; mt++) {
                    mma16816(acc[mt][nt], ah2[mt], bf[nt][0], bf[nt][1]);   // hi*hi
                    if (NPASS == 3)
                        mma16816(acc[mt][nt], al2[mt], bf[nt][0], bf[nt][1]); // lo*hi
                }
            // ---- B-lo pass ----
            if (NPASS >= 2) {
#pragma unroll
                for (int p = 0; p < 4; p++) {
                    uint32_t r[4];
                    ldsm4(r, baseBL + bro + p * (16 * RS) + kb + bko);
                    bf[2 * p][0] = r[0]; bf[2 * p][1] = r[1];
                    bf[2 * p + 1][0] = r[2]; bf[2 * p + 1][1] = r[3];
                }
#pragma unroll
                for (int nt = 0; nt < 8; nt++)
#pragma unroll
                    for (int mt = 0; mt < 2; mt++)
                        mma16816(acc[mt][nt], ah2[mt], bf[nt][0], bf[nt][1]); // hi*lo
            }
        }
        __syncthreads();
    }

    // ---- epilogue ----
#pragma unroll
    for (int nt = 0; nt < 8; nt++) {
        const int col = bn + wn * 64 + nt * 8 + 2 * tg;
        float2 bv = *(const float2*)&bias[col];
#pragma unroll
        for (int mt = 0; mt < 2; mt++) {
            const int row0 = bm + wm * 32 + mt * 16 + g;
            float v0 = acc[mt][nt][0] + bv.x;
            float v1 = acc[mt][nt][1] + bv.y;
            float v2 = acc[mt][nt][2] + bv.x;
            float v3 = acc[mt][nt][3] + bv.y;
            if (dorelu) {
                v0 = fmaxf(v0, 0.f); v1 = fmaxf(v1, 0.f);
                v2 = fmaxf(v2, 0.f); v3 = fmaxf(v3, 0.f);
            }
            if (Ch) {
                if (Cl) {
                    if (row0 < M) {
                        __half h0 = __float2half_rn(v0), h1 = __float2half_rn(v1);
                        *(uint32_t*)(Ch + (size_t)row0 * ldc + col) =
                            ((uint32_t)__half_as_ushort(h1) << 16) | (uint32_t)__half_as_ushort(h0);
                        *(uint32_t*)(Cl + (size_t)row0 * ldc + col) =
                            packh(v0 - __half2float(h0), v1 - __half2float(h1));
                    }
                    if (row0 + 8 < M) {
                        __half h2 = __float2half_rn(v2), h3 = __float2half_rn(v3);
                        *(uint32_t*)(Ch + (size_t)(row0 + 8) * ldc + col) =
                            ((uint32_t)__half_as_ushort(h3) << 16) | (uint32_t)__half_as_ushort(h2);
                        *(uint32_t*)(Cl + (size_t)(row0 + 8) * ldc + col) =
                            packh(v2 - __half2float(h2), v3 - __half2float(h3));
                    }
                } else {
                    if (row0 < M)
                        *(uint32_t*)(Ch + (size_t)row0 * ldc + col) = packh(v0, v1);
                    if (row0 + 8 < M)
                        *(uint32_t*)(Ch + (size_t)(row0 + 8) * ldc + col) = packh(v2, v3);
                }
            } else {
                if (row0 < M)
                    *(float2*)&Cf[(size_t)row0 * ldc + col] = make_float2(v0, v1);
                if (row0 + 8 < M)
                    *(float2*)&Cf[(size_t)(row0 + 8) * ldc + col] = make_float2(v2, v3);
            }
        }
    }
}

// ---------------- host launcher ----------------
template <int NPASS>
static void mgemm(const __half* Ah, const __half* Al, const __half* Bh, const __half* Bl,
                  const float* bias, float* Cf, __half* Ch, __half* Cl,
                  int ldc, int M, int N, int K) {
    constexpr int NT = (NPASS == 3) ? 4 : ((NPASS == 2) ? 3 : 2);
    dim3 grid(N / 128, (M + 127) / 128);
    mgemm_kernel<NPASS><<<grid, 256, 2 * NT * TILEB>>>(Ah, Al, Bh, Bl, bias, Cf, Ch, Cl,
                                                       ldc, M, N, K, 0);
}

extern "C" void kernel_launch(void* const* d_in, const int* in_sizes, int n_in,
                              void* d_out, int out_size) {
    (void)in_sizes; (void)n_in; (void)out_size;

    const float* text   = (const float*)d_in[0];
    const float* wm_x   = (const float*)d_in[1];
    const int*   wm_ei  = (const int*)  d_in[2];
    const int*   t2n    = (const int*)  d_in[3];
    const int*   fids   = (const int*)  d_in[4];
    const int*   f_ei   = (const int*)  d_in[5];
    // d_in[6] extra_emb: unreachable (indices always >= 2)
    const float* wm_W1  = (const float*)d_in[7];
    const float* wm_b1  = (const float*)d_in[8];
    const float* wm_W2  = (const float*)d_in[9];
    const float* wm_b2  = (const float*)d_in[10];
    const float* f_W1   = (const float*)d_in[11];
    const float* f_b1   = (const float*)d_in[12];
    const float* f_W2   = (const float*)d_in[13];
    const float* f_b2   = (const float*)d_in[14];
    const float* fc1_W  = (const float*)d_in[15];
    const float* fc1_b  = (const float*)d_in[16];
    const float* fc3_W  = (const float*)d_in[17];
    const float* fc3_b  = (const float*)d_in[18];
    float* out = (float*)d_out;

    cudaFuncSetAttribute(mgemm_kernel<3>, cudaFuncAttributeMaxDynamicSharedMemorySize, 8 * TILEB);
    cudaFuncSetAttribute(mgemm_kernel<2>, cudaFuncAttributeMaxDynamicSharedMemorySize, 6 * TILEB);
    cudaFuncSetAttribute(mgemm_kernel<1>, cudaFuncAttributeMaxDynamicSharedMemorySize, 4 * TILEB);

    float *fM, *fH, *zb;
    __half *th, *geh, *ah, *al, *gteh, *gtel, *c1h, *c1l, *c3h;
    __half *w1h, *w1l, *w2h, *w2l, *gh1, *gl1, *gh2, *gl2, *p1h, *p1l, *p3h, *p3l;
    int *wrp, *wcur, *wcol, *frp, *fcur, *fcol;
    cudaGetSymbolAddress((void**)&fM,   g_fM);
    cudaGetSymbolAddress((void**)&fH,   g_fH);
    cudaGetSymbolAddress((void**)&zb,   g_zerob);
    cudaGetSymbolAddress((void**)&th,   g_th);
    cudaGetSymbolAddress((void**)&geh,  g_geh);
    cudaGetSymbolAddress((void**)&ah,   g_ah);
    cudaGetSymbolAddress((void**)&al,   g_al);
    cudaGetSymbolAddress((void**)&gteh, g_gteh);
    cudaGetSymbolAddress((void**)&gtel, g_gtel);
    cudaGetSymbolAddress((void**)&c1h,  g_c1h);
    cudaGetSymbolAddress((void**)&c1l,  g_c1l);
    cudaGetSymbolAddress((void**)&c3h,  g_c3h);
    cudaGetSymbolAddress((void**)&w1h,  g_w1h);
    cudaGetSymbolAddress((void**)&w1l,  g_w1l);
    cudaGetSymbolAddress((void**)&w2h,  g_w2h);
    cudaGetSymbolAddress((void**)&w2l,  g_w2l);
    cudaGetSymbolAddress((void**)&gh1,  g_g1h);
    cudaGetSymbolAddress((void**)&gl1,  g_g1l);
    cudaGetSymbolAddress((void**)&gh2,  g_g2h);
    cudaGetSymbolAddress((void**)&gl2,  g_g2l);
    cudaGetSymbolAddress((void**)&p1h,  g_fc1h);
    cudaGetSymbolAddress((void**)&p1l,  g_fc1l);
    cudaGetSymbolAddress((void**)&p3h,  g_fc3h);
    cudaGetSymbolAddress((void**)&p3l,  g_fc3l);
    cudaGetSymbolAddress((void**)&wrp,  g_wm_rowptr);
    cudaGetSymbolAddress((void**)&wcur, g_wm_cur);
    cudaGetSymbolAddress((void**)&wcol, g_wm_col);
    cudaGetSymbolAddress((void**)&frp,  g_f_rowptr);
    cudaGetSymbolAddress((void**)&fcur, g_f_cur);
    cudaGetSymbolAddress((void**)&fcol, g_f_col);

    const dim3 bSp(64, 4);
    const dim3 wcb(32, 8);

    // ===== WM layer 1 (2-pass; fp16 t) =====
    split_x_hi_kernel<<<(NWM * G4 + 255) / 256, 256>>>((const float4*)wm_x, ah, NWM * G4);
    wconv_kernel<<<dim3(GG / 32, GG / 32), wcb>>>(wm_W1, w1h, w1l, GG, GG);
    zero_int_kernel<<<(NWM + 255) / 256, 256>>>(wcur, NWM);
    hist_kernel<<<(EWM + 255) / 256, 256>>>(wm_ei + EWM, wcur, EWM);
    scan_kernel<<<1, 1024>>>(wcur, wrp, NWM, EWM);
    mgemm<2>(ah, ah, w1h, w1l, zb, nullptr, th, nullptr, GG, NWM, GG, GG);
    fill_kernel<<<(EWM + 255) / 256, 256>>>(wm_ei, wm_ei + EWM, wcur, wcol, EWM);
    spmm_post_h16_kernel<<<(NWM + 3) / 4, bSp>>>((const uint2*)th, wrp, wcol, wm_b1,
                                                 ah, GG, 0, NWM);
    // ===== WM layer 2 (2-pass; fp16 t; fp16 graph embeddings) =====
    wconv_kernel<<<dim3(GG / 32, GG / 32), wcb>>>(wm_W2, w2h, w2l, GG, GG);
    mgemm<2>(ah, ah, w2h, w2l, zb, nullptr, th, nullptr, GG, NWM, GG, GG);
    spmm_post_h16_kernel<<<(NWM + 3) / 4, bSp>>>((const uint2*)th, wrp, wcol, wm_b2,
                                                 geh, GG, 0, NWM);
    // geh = graph_embeddings [NWM, G] fp16

    // ===== token concept sum + text conversion -> cat buffers =====
    gather4sum_h_kernel<<<(NF + 3) / 4, bSp>>>((const uint2*)geh, t2n, c1h, c1l, c3h, NF);
    textconv_kernel<<<(NF * PLM4 + 255) / 256, 256>>>((const float4*)text, c1h, c1l, c3h, NF);

    // ===== fc1 (3-pass, split output) =====
    wconv_kernel<<<dim3(GG / 32, CAT1 / 32), wcb>>>(fc1_W, p1h, p1l, CAT1, GG);
    mgemm<3>(c1h, c1l, p1h, p1l, fc1_b, nullptr, gteh, gtel, GG, NF, GG, CAT1);

    // ===== FSTM CSR + gather =====
    zero_int_kernel<<<(NF + 255) / 256, 256>>>(fcur, NF);
    hist_kernel<<<(EF + 255) / 256, 256>>>(f_ei + EF, fcur, EF);
    scan_kernel<<<1, 1024>>>(fcur, frp, NF, EF);
    fill_kernel<<<(EF + 255) / 256, 256>>>(f_ei, f_ei + EF, fcur, fcol, EF);
    gather_split_kernel<<<(NF + 3) / 4, bSp>>>((const uint2*)gteh, (const uint2*)gtel, fids,
                                               (uint2*)ah, (uint2*)al, NF);

    // ===== FSTM layer 1 (3-pass, fp32 t) =====
    wconv_kernel<<<dim3(GG / 32, GG / 32), wcb>>>(f_W1, gh1, gl1, GG, GG);
    mgemm<3>(ah, al, gh1, gl1, zb, fM, nullptr, nullptr, GG, NF, GG, GG);
    spmm_post_split_kernel<<<(NF + 3) / 4, bSp>>>((const float4*)fM, frp, fcol, f_b1,
                                                  ah, al, GG, 0, NF);
    // ===== FSTM layer 2 (3-pass; hi-only output straight into cat3 @ col 1024) =====
    wconv_kernel<<<dim3(GG / 32, GG / 32), wcb>>>(f_W2, gh2, gl2, GG, GG);
    mgemm<3>(ah, al, gh2, gl2, zb, fH, nullptr, nullptr, GG, NF, GG, GG);
    spmm_post_split_kernel<<<(NF + 3) / 4, bSp>>>((const float4*)fH, frp, fcol, f_b2,
                                                  c3h, nullptr, CAT3, PLM + GG, NF);

    // ===== fc3 -> out (1-pass plain fp16) =====
    wconv_kernel<<<dim3(PLM / 32, CAT3 / 32), wcb>>>(fc3_W, p3h, p3l, CAT3, PLM);
    mgemm<1>(c3h, c3h, p3h, p3h, fc3_b, out, nullptr, nullptr, PLM, NF, PLM, CAT3);
}

// round 9
// speedup vs baseline: 1.6865x; 1.1317x over previous
#include <cuda_runtime.h>
#include <cuda_fp16.h>
#include <cstdint>

// ---------------- problem constants ----------------
#define PLM   768
#define GG    256
#define NWM   50000
#define EWM   800000
#define NF    16384           // B*S
#define EF    131072
#define KSLOT 4
#define G4    (GG/4)          // 64 float4 per G-row
#define PLM4  (PLM/4)         // 192 float4 per PLM-row
#define CAT3  (PLM + 2*GG)    // 1280
#define CAT1  (GG + PLM)      // 1024

// ---------------- device scratch (no runtime alloc allowed) ----------------
__device__ __align__(16) float g_fM  [(size_t)NF * GG];    // fstm t (fp32)
__device__ __align__(16) float g_zerob[PLM];               // zero bias (BSS)
// fp16 buffers (plain fp16 activations; exact-B 2-pass makes lo planes unnecessary)
__device__ __align__(16) __half g_th [(size_t)NWM * GG];   // WM / fstm t (fp16, WM-sized)
__device__ __align__(16) __half g_geh[(size_t)NWM * GG];   // graph embeddings (fp16)
__device__ __align__(16) __half g_ah [(size_t)NWM * GG];   // activations (fp16)
__device__ __align__(16) __half g_gteh[(size_t)NF * GG];   // graph_text_embed (fp16)
__device__ __align__(16) __half g_c1h[(size_t)NF * CAT1];
__device__ __align__(16) __half g_c3h[(size_t)NF * CAT3];
// fp16 transposed weights [N, K] (hi; lo only where 2-pass used)
__device__ __align__(16) __half g_w1h[GG * GG];
__device__ __align__(16) __half g_w2h[GG * GG];
__device__ __align__(16) __half g_g1h[GG * GG];
__device__ __align__(16) __half g_g1l[GG * GG];
__device__ __align__(16) __half g_g2h[GG * GG];
__device__ __align__(16) __half g_g2l[GG * GG];
__device__ __align__(16) __half g_fc1h[GG * CAT1];
__device__ __align__(16) __half g_fc1l[GG * CAT1];
__device__ __align__(16) __half g_fc3h[PLM * CAT3];
// CSR
__device__ int g_wm_rowptr[NWM + 1];
__device__ int g_wm_cur[NWM];
__device__ int g_wm_col[EWM];
__device__ int g_f_rowptr[NF + 1];
__device__ int g_f_cur[NF];
__device__ int g_f_col[EF];

// ---------------- helpers ----------------
__device__ __forceinline__ uint32_t smem_u32(const void* p) {
    uint32_t a;
    asm("{ .reg .u64 t; cvta.to.shared.u64 t, %1; cvt.u32.u64 %0, t; }" : "=r"(a) : "l"(p));
    return a;
}
__device__ __forceinline__ void cp16(uint32_t dst, const void* src, uint32_t srcsize) {
    asm volatile("cp.async.cg.shared.global [%0], [%1], 16, %2;"
                 :: "r"(dst), "l"(src), "r"(srcsize) : "memory");
}
#define CP_COMMIT() asm volatile("cp.async.commit_group;" ::: "memory")
#define CP_WAIT(n)  asm volatile("cp.async.wait_group %0;" :: "n"(n) : "memory")

__device__ __forceinline__ void ldsm4(uint32_t* r, uint32_t addr) {
    asm volatile("ldmatrix.sync.aligned.m8n8.x4.shared.b16 {%0,%1,%2,%3}, [%4];"
                 : "=r"(r[0]), "=r"(r[1]), "=r"(r[2]), "=r"(r[3]) : "r"(addr));
}
__device__ __forceinline__ void mma16816(float* c, const uint32_t* a, uint32_t b0, uint32_t b1) {
    asm volatile(
        "mma.sync.aligned.m16n8k16.row.col.f32.f16.f16.f32 "
        "{%0,%1,%2,%3}, {%4,%5,%6,%7}, {%8,%9}, {%0,%1,%2,%3};\n"
        : "+f"(c[0]), "+f"(c[1]), "+f"(c[2]), "+f"(c[3])
        : "r"(a[0]), "r"(a[1]), "r"(a[2]), "r"(a[3]), "r"(b0), "r"(b1));
}

__device__ __forceinline__ uint32_t packh(float a, float b) {
    __half ha = __float2half_rn(a), hb = __float2half_rn(b);
    return ((uint32_t)__half_as_ushort(hb) << 16) | (uint32_t)__half_as_ushort(ha);
}
__device__ __forceinline__ uint2 pack4h(float4 v) {
    uint2 hp;
    hp.x = packh(v.x, v.y);
    hp.y = packh(v.z, v.w);
    return hp;
}
__device__ __forceinline__ float4 h4_to_f4(uint2 u) {
    __half2 a = *(__half2*)&u.x, b = *(__half2*)&u.y;
    float2 fa = __half22float2(a), fb = __half22float2(b);
    return make_float4(fa.x, fa.y, fb.x, fb.y);
}

// ---------------- CSR build kernels ----------------
__global__ void zero_int_kernel(int* __restrict__ p, int n) {
    int i = blockIdx.x * blockDim.x + threadIdx.x;
    if (i < n) p[i] = 0;
}
__global__ void hist_kernel(const int* __restrict__ dst, int* __restrict__ cnt, int E) {
    int e = blockIdx.x * blockDim.x + threadIdx.x;
    if (e < E) atomicAdd(&cnt[dst[e]], 1);
}
__global__ void scan_kernel(int* __restrict__ cnt_cur, int* __restrict__ rowptr, int N, int E) {
    __shared__ int sh[1024];
    int tid = threadIdx.x;
    int chunk = (N + 1023) >> 10;
    int s0 = tid * chunk;
    int s1 = s0 + chunk; if (s1 > N) s1 = N;
    int s = 0;
    for (int i = s0; i < s1; i++) s += cnt_cur[i];
    sh[tid] = s;
    __syncthreads();
    for (int off = 1; off < 1024; off <<= 1) {
        int v = (tid >= off) ? sh[tid - off] : 0;
        __syncthreads();
        sh[tid] += v;
        __syncthreads();
    }
    int run = sh[tid] - s;
    for (int i = s0; i < s1; i++) {
        int c = cnt_cur[i];
        rowptr[i]  = run;
        cnt_cur[i] = run;
        run += c;
    }
    if (tid == 0) rowptr[N] = E;
}
__global__ void fill_kernel(const int* __restrict__ src, const int* __restrict__ dst,
                            int* __restrict__ cur, int* __restrict__ col, int E) {
    int e = blockIdx.x * blockDim.x + threadIdx.x;
    if (e < E) {
        int d = dst[e];
        int p = atomicAdd(&cur[d], 1);
        col[p] = src[e];
    }
}

// ---------------- elementwise / gather kernels ----------------
__global__ void split_x_hi_kernel(const float4* __restrict__ x,
                                  __half* __restrict__ oh, int n4) {
    int idx = blockIdx.x * blockDim.x + threadIdx.x;
    if (idx >= n4) return;
    *(uint2*)(oh + 4 * (size_t)idx) = pack4h(x[idx]);
}

// fp16-t aggregation: v = relu(t[n] + sum t[src] + bias); write fp16 (strided)
__global__ void spmm_post_h16_kernel(const uint2* __restrict__ t,
                                     const int* __restrict__ rowptr,
                                     const int* __restrict__ col,
                                     const float* __restrict__ bias,
                                     __half* __restrict__ oh,
                                     size_t ldo, size_t coff, int n) {
    int node = blockIdx.x * blockDim.y + threadIdx.y;
    if (node >= n) return;
    int x = threadIdx.x;  // 0..63 (uint2 = 4 halves)
    float4 acc = h4_to_f4(t[(size_t)node * 64 + x]);
    int e  = rowptr[node];
    int e1 = rowptr[node + 1];
    for (; e + 4 <= e1; e += 4) {
        int s0 = __ldg(&col[e]), s1 = __ldg(&col[e + 1]);
        int s2 = __ldg(&col[e + 2]), s3 = __ldg(&col[e + 3]);
        float4 v0 = h4_to_f4(__ldg(&t[(size_t)s0 * 64 + x]));
        float4 v1 = h4_to_f4(__ldg(&t[(size_t)s1 * 64 + x]));
        float4 v2 = h4_to_f4(__ldg(&t[(size_t)s2 * 64 + x]));
        float4 v3 = h4_to_f4(__ldg(&t[(size_t)s3 * 64 + x]));
        acc.x += v0.x + v1.x + v2.x + v3.x;
        acc.y += v0.y + v1.y + v2.y + v3.y;
        acc.z += v0.z + v1.z + v2.z + v3.z;
        acc.w += v0.w + v1.w + v2.w + v3.w;
    }
    for (; e < e1; ++e) {
        int s = __ldg(&col[e]);
        float4 v = h4_to_f4(__ldg(&t[(size_t)s * 64 + x]));
        acc.x += v.x; acc.y += v.y; acc.z += v.z; acc.w += v.w;
    }
    float4 bv = *(const float4*)&bias[4 * x];
    acc.x = fmaxf(acc.x + bv.x, 0.f);
    acc.y = fmaxf(acc.y + bv.y, 0.f);
    acc.z = fmaxf(acc.z + bv.z, 0.f);
    acc.w = fmaxf(acc.w + bv.w, 0.f);
    *(uint2*)(oh + (size_t)node * ldo + coff + 4 * x) = pack4h(acc);
}

// fp32-t aggregation; write fp16 (strided)
__global__ void spmm_post_f32_kernel(const float4* __restrict__ t,
                                     const int* __restrict__ rowptr,
                                     const int* __restrict__ col,
                                     const float* __restrict__ bias,
                                     __half* __restrict__ oh,
                                     size_t ldo, size_t coff, int n) {
    int node = blockIdx.x * blockDim.y + threadIdx.y;
    if (node >= n) return;
    int x = threadIdx.x;  // 0..63
    float4 acc = t[(size_t)node * G4 + x];
    int e  = rowptr[node];
    int e1 = rowptr[node + 1];
    for (; e + 4 <= e1; e += 4) {
        int s0 = __ldg(&col[e]), s1 = __ldg(&col[e + 1]);
        int s2 = __ldg(&col[e + 2]), s3 = __ldg(&col[e + 3]);
        float4 v0 = __ldg(&t[(size_t)s0 * G4 + x]);
        float4 v1 = __ldg(&t[(size_t)s1 * G4 + x]);
        float4 v2 = __ldg(&t[(size_t)s2 * G4 + x]);
        float4 v3 = __ldg(&t[(size_t)s3 * G4 + x]);
        acc.x += v0.x + v1.x + v2.x + v3.x;
        acc.y += v0.y + v1.y + v2.y + v3.y;
        acc.z += v0.z + v1.z + v2.z + v3.z;
        acc.w += v0.w + v1.w + v2.w + v3.w;
    }
    for (; e < e1; ++e) {
        int s = __ldg(&col[e]);
        float4 v = __ldg(&t[(size_t)s * G4 + x]);
        acc.x += v.x; acc.y += v.y; acc.z += v.z; acc.w += v.w;
    }
    float4 bv = *(const float4*)&bias[4 * x];
    acc.x = fmaxf(acc.x + bv.x, 0.f);
    acc.y = fmaxf(acc.y + bv.y, 0.f);
    acc.z = fmaxf(acc.z + bv.z, 0.f);
    acc.w = fmaxf(acc.w + bv.w, 0.f);
    *(uint2*)(oh + (size_t)node * ldo + coff + 4 * x) = pack4h(acc);
}

// tmp[row] = sum_k ge16[t2n[row*4+k]]; fp16 into cat1 @col0 and cat3 @col768
__global__ void gather4sum_h_kernel(const uint2* __restrict__ ge,
                                    const int* __restrict__ t2n,
                                    __half* __restrict__ c1h,
                                    __half* __restrict__ c3h, int rows) {
    int row = blockIdx.x * blockDim.y + threadIdx.y;
    if (row >= rows) return;
    int x = threadIdx.x;
    float4 acc = make_float4(0.f, 0.f, 0.f, 0.f);
#pragma unroll
    for (int k = 0; k < KSLOT; k++) {
        int idx = __ldg(&t2n[row * KSLOT + k]);
        float4 v = h4_to_f4(__ldg(&ge[(size_t)idx * 64 + x]));
        acc.x += v.x; acc.y += v.y; acc.z += v.z; acc.w += v.w;
    }
    uint2 hp = pack4h(acc);
    *(uint2*)(c1h + (size_t)row * CAT1 + 4 * x) = hp;
    *(uint2*)(c3h + (size_t)row * CAT3 + PLM + 4 * x) = hp;
}

// gather fp16 rows: dst[row] = src[ids[row]]
__global__ void gather_h_kernel(const uint2* __restrict__ src,
                                const int* __restrict__ ids,
                                uint2* __restrict__ dst, int rows) {
    int row = blockIdx.x * blockDim.y + threadIdx.y;
    if (row >= rows) return;
    int id = ids[row];
    int x = threadIdx.x;  // 0..63
    dst[(size_t)row * 64 + x] = src[(size_t)id * 64 + x];
}

// text fp32 -> fp16 into cat1 @col 256 and cat3 @col 0
__global__ void textconv_kernel(const float4* __restrict__ text,
                                __half* __restrict__ c1h,
                                __half* __restrict__ c3h, int rows) {
    int idx = blockIdx.x * blockDim.x + threadIdx.x;
    if (idx >= rows * PLM4) return;
    int row = idx / PLM4;
    int c   = idx - row * PLM4;
    uint2 hp = pack4h(text[idx]);
    *(uint2*)(c1h + (size_t)row * CAT1 + GG + 4 * c) = hp;
    *(uint2*)(c3h + (size_t)row * CAT3 + 4 * c) = hp;
}

// weight [K,N] fp32 -> transposed [N,K] fp16 hi (+ optional lo)
__global__ void wconv_kernel(const float* __restrict__ W,
                             __half* __restrict__ Wh, __half* __restrict__ Wl,
                             int Kd, int Nd) {
    __shared__ float t[32][33];
    int kb = blockIdx.y * 32, nb = blockIdx.x * 32;
#pragma unroll
    for (int j = 0; j < 32; j += 8) {
        int k = kb + threadIdx.y + j, n = nb + threadIdx.x;
        t[threadIdx.y + j][threadIdx.x] = W[(size_t)k * Nd + n];
    }
    __syncthreads();
#pragma unroll
    for (int j = 0; j < 32; j += 8) {
        int n = nb + threadIdx.y + j, k = kb + threadIdx.x;
        float x = t[threadIdx.x][threadIdx.y + j];
        __half h = __float2half_rn(x);
        Wh[(size_t)n * Kd + k] = h;
        if (Wl) Wl[(size_t)n * Kd + k] = __float2half_rn(x - __half2float(h));
    }
}

// ---------------- legacy-MMA fp16 GEMM ----------------
// NPASS=2: ah*bh + ah*bl (exact in B; A plain fp16). NPASS=1: ah*bh.
// Tiles: AH=0, BH=1, [BL=2 if NPASS==2].
#define RS     80
#define TILEB  (128 * RS)            // 10240

template <int NPASS>
__global__ __launch_bounds__(256, 2)
void mgemm_kernel(const __half* __restrict__ Ah,
                  const __half* __restrict__ Bh, const __half* __restrict__ Bl,
                  const float* __restrict__ bias,
                  float* __restrict__ Cf, __half* __restrict__ Ch,
                  int ldc, int M, int N, int K) {
    constexpr int NT = (NPASS == 2) ? 3 : 2;
    extern __shared__ char smem[];
    const uint32_t sb = smem_u32(smem);
    const int tid = threadIdx.x, lane = tid & 31, wid = tid >> 5;
    const int wm = wid & 3, wn = wid >> 2;
    const int bm = blockIdx.y * 128, bn = blockIdx.x * 128;
    const int g = lane >> 2, tg = lane & 3;

    const int srow = tid >> 1;
    const int sc   = (tid & 1) * 2;
    const int arow = bm + srow;
    const bool aok = arow < M;
    const int arA  = aok ? arow : 0;
    const uint32_t asz = aok ? 16u : 0u;
    const int brow = bn + srow;
    const uint32_t doff = srow * RS + sc * 16;

    auto soff = [&](int b, int t) -> uint32_t { return (uint32_t)((b * NT + t) * TILEB); };

    auto stage = [&](int kt, int b) {
        const size_t ko = (size_t)kt * 32 + sc * 8;
        const __half* pAh = Ah + (size_t)arA * K + ko;
        const __half* pBh = Bh + (size_t)brow * K + ko;
        cp16(sb + soff(b, 0) + doff,      pAh,     asz);
        cp16(sb + soff(b, 0) + doff + 16, pAh + 8, asz);
        cp16(sb + soff(b, 1) + doff,      pBh,     16u);
        cp16(sb + soff(b, 1) + doff + 16, pBh + 8, 16u);
        if (NPASS == 2) {
            const __half* pBl = Bl + (size_t)brow * K + ko;
            cp16(sb + soff(b, 2) + doff,      pBl,     16u);
            cp16(sb + soff(b, 2) + doff + 16, pBl + 8, 16u);
        }
    };

    const uint32_t aro = (wm * 32 + (lane & 7) + ((lane >> 3) & 1) * 8) * RS;
    const uint32_t ako = ((lane >> 4) & 1) * 16;
    const uint32_t bro = (wn * 64 + (lane & 7) + ((lane >> 4) & 1) * 8) * RS;
    const uint32_t bko = ((lane >> 3) & 1) * 16;

    float acc[2][8][4];
#pragma unroll
    for (int i = 0; i < 2; i++)
#pragma unroll
        for (int j = 0; j < 8; j++)
#pragma unroll
            for (int q = 0; q < 4; q++) acc[i][j][q] = 0.f;

    const int nk = K >> 5;
    stage(0, 0);
    CP_COMMIT();

    for (int t = 0; t < nk; t++) {
        const int b = t & 1;
        if (t + 1 < nk) {
            stage(t + 1, b ^ 1);
            CP_COMMIT();
            CP_WAIT(1);
        } else {
            CP_WAIT(0);
        }
        __syncthreads();

        const uint32_t baseAH = sb + soff(b, 0);
        const uint32_t baseBH = sb + soff(b, 1);
        const uint32_t baseBL = sb + soff(b, 2);

#pragma unroll
        for (int s = 0; s < 2; s++) {
            const uint32_t kb = s * 32;
            uint32_t ah2[2][4], bf[8][2];
#pragma unroll
            for (int mt = 0; mt < 2; mt++)
                ldsm4(ah2[mt], baseAH + aro + mt * (16 * RS) + kb + ako);
            // ---- B-hi pass ----
#pragma unroll
            for (int p = 0; p < 4; p++) {
                uint32_t r[4];
                ldsm4(r, baseBH + bro + p * (16 * RS) + kb + bko);
                bf[2 * p][0] = r[0]; bf[2 * p][1] = r[1];
                bf[2 * p + 1][0] = r[2]; bf[2 * p + 1][1] = r[3];
            }
#pragma unroll
            for (int nt = 0; nt < 8; nt++)
#pragma unroll
                for (int mt = 0; mt < 2; mt++)
                    mma16816(acc[mt][nt], ah2[mt], bf[nt][0], bf[nt][1]);   // hi*hi
            // ---- B-lo pass ----
            if (NPASS == 2) {
#pragma unroll
                for (int p = 0; p < 4; p++) {
                    uint32_t r[4];
                    ldsm4(r, baseBL + bro + p * (16 * RS) + kb + bko);
                    bf[2 * p][0] = r[0]; bf[2 * p][1] = r[1];
                    bf[2 * p + 1][0] = r[2]; bf[2 * p + 1][1] = r[3];
                }
#pragma unroll
                for (int nt = 0; nt < 8; nt++)
#pragma unroll
                    for (int mt = 0; mt < 2; mt++)
                        mma16816(acc[mt][nt], ah2[mt], bf[nt][0], bf[nt][1]); // hi*lo
            }
        }
        __syncthreads();
    }

    // ---- epilogue ----
#pragma unroll
    for (int nt = 0; nt < 8; nt++) {
        const int col = bn + wn * 64 + nt * 8 + 2 * tg;
        float2 bv = *(const float2*)&bias[col];
#pragma unroll
        for (int mt = 0; mt < 2; mt++) {
            const int row0 = bm + wm * 32 + mt * 16 + g;
            float v0 = acc[mt][nt][0] + bv.x;
            float v1 = acc[mt][nt][1] + bv.y;
            float v2 = acc[mt][nt][2] + bv.x;
            float v3 = acc[mt][nt][3] + bv.y;
            if (Ch) {
                if (row0 < M)
                    *(uint32_t*)(Ch + (size_t)row0 * ldc + col) = packh(v0, v1);
                if (row0 + 8 < M)
                    *(uint32_t*)(Ch + (size_t)(row0 + 8) * ldc + col) = packh(v2, v3);
            } else {
                if (row0 < M)
                    *(float2*)&Cf[(size_t)row0 * ldc + col] = make_float2(v0, v1);
                if (row0 + 8 < M)
                    *(float2*)&Cf[(size_t)(row0 + 8) * ldc + col] = make_float2(v2, v3);
            }
        }
    }
}

// ---------------- host launcher ----------------
template <int NPASS>
static void mgemm(const __half* Ah, const __half* Bh, const __half* Bl,
                  const float* bias, float* Cf, __half* Ch,
                  int ldc, int M, int N, int K) {
    constexpr int NT = (NPASS == 2) ? 3 : 2;
    dim3 grid(N / 128, (M + 127) / 128);
    mgemm_kernel<NPASS><<<grid, 256, 2 * NT * TILEB>>>(Ah, Bh, Bl, bias, Cf, Ch,
                                                       ldc, M, N, K);
}

extern "C" void kernel_launch(void* const* d_in, const int* in_sizes, int n_in,
                              void* d_out, int out_size) {
    (void)in_sizes; (void)n_in; (void)out_size;

    const float* text   = (const float*)d_in[0];
    const float* wm_x   = (const float*)d_in[1];
    const int*   wm_ei  = (const int*)  d_in[2];
    const int*   t2n    = (const int*)  d_in[3];
    const int*   fids   = (const int*)  d_in[4];
    const int*   f_ei   = (const int*)  d_in[5];
    // d_in[6] extra_emb: unreachable (indices always >= 2)
    const float* wm_W1  = (const float*)d_in[7];
    const float* wm_b1  = (const float*)d_in[8];
    const float* wm_W2  = (const float*)d_in[9];
    const float* wm_b2  = (const float*)d_in[10];
    const float* f_W1   = (const float*)d_in[11];
    const float* f_b1   = (const float*)d_in[12];
    const float* f_W2   = (const float*)d_in[13];
    const float* f_b2   = (const float*)d_in[14];
    const float* fc1_W  = (const float*)d_in[15];
    const float* fc1_b  = (const float*)d_in[16];
    const float* fc3_W  = (const float*)d_in[17];
    const float* fc3_b  = (const float*)d_in[18];
    float* out = (float*)d_out;

    cudaFuncSetAttribute(mgemm_kernel<2>, cudaFuncAttributeMaxDynamicSharedMemorySize, 6 * TILEB);
    cudaFuncSetAttribute(mgemm_kernel<1>, cudaFuncAttributeMaxDynamicSharedMemorySize, 4 * TILEB);

    float *fM, *zb;
    __half *th, *geh, *ah, *gteh, *c1h, *c3h;
    __half *w1h, *w2h, *gh1, *gl1, *gh2, *gl2, *p1h, *p1l, *p3h;
    int *wrp, *wcur, *wcol, *frp, *fcur, *fcol;
    cudaGetSymbolAddress((void**)&fM,   g_fM);
    cudaGetSymbolAddress((void**)&zb,   g_zerob);
    cudaGetSymbolAddress((void**)&th,   g_th);
    cudaGetSymbolAddress((void**)&geh,  g_geh);
    cudaGetSymbolAddress((void**)&ah,   g_ah);
    cudaGetSymbolAddress((void**)&gteh, g_gteh);
    cudaGetSymbolAddress((void**)&c1h,  g_c1h);
    cudaGetSymbolAddress((void**)&c3h,  g_c3h);
    cudaGetSymbolAddress((void**)&w1h,  g_w1h);
    cudaGetSymbolAddress((void**)&w2h,  g_w2h);
    cudaGetSymbolAddress((void**)&gh1,  g_g1h);
    cudaGetSymbolAddress((void**)&gl1,  g_g1l);
    cudaGetSymbolAddress((void**)&gh2,  g_g2h);
    cudaGetSymbolAddress((void**)&gl2,  g_g2l);
    cudaGetSymbolAddress((void**)&p1h,  g_fc1h);
    cudaGetSymbolAddress((void**)&p1l,  g_fc1l);
    cudaGetSymbolAddress((void**)&p3h,  g_fc3h);
    cudaGetSymbolAddress((void**)&wrp,  g_wm_rowptr);
    cudaGetSymbolAddress((void**)&wcur, g_wm_cur);
    cudaGetSymbolAddress((void**)&wcol, g_wm_col);
    cudaGetSymbolAddress((void**)&frp,  g_f_rowptr);
    cudaGetSymbolAddress((void**)&fcur, g_f_cur);
    cudaGetSymbolAddress((void**)&fcol, g_f_col);

    const dim3 bSp(64, 4);
    const dim3 wcb(32, 8);

    // ===== WM layer 1 (1-pass; fp16 everywhere) — GEMM is launch #6 for ncu =====
    split_x_hi_kernel<<<(NWM * G4 + 255) / 256, 256>>>((const float4*)wm_x, ah, NWM * G4); // 1
    wconv_kernel<<<dim3(GG / 32, GG / 32), wcb>>>(wm_W1, w1h, nullptr, GG, GG);            // 2
    zero_int_kernel<<<(NWM + 255) / 256, 256>>>(wcur, NWM);                                // 3
    hist_kernel<<<(EWM + 255) / 256, 256>>>(wm_ei + EWM, wcur, EWM);                       // 4
    scan_kernel<<<1, 1024>>>(wcur, wrp, NWM, EWM);                                         // 5
    mgemm<1>(ah, w1h, nullptr, zb, nullptr, th, GG, NWM, GG, GG);                          // 6 <- ncu
    fill_kernel<<<(EWM + 255) / 256, 256>>>(wm_ei, wm_ei + EWM, wcur, wcol, EWM);          // 7
    spmm_post_h16_kernel<<<(NWM + 3) / 4, bSp>>>((const uint2*)th, wrp, wcol, wm_b1,
                                                 ah, GG, 0, NWM);
    // ===== WM layer 2 (1-pass) =====
    wconv_kernel<<<dim3(GG / 32, GG / 32), wcb>>>(wm_W2, w2h, nullptr, GG, GG);
    mgemm<1>(ah, w2h, nullptr, zb, nullptr, th, GG, NWM, GG, GG);
    spmm_post_h16_kernel<<<(NWM + 3) / 4, bSp>>>((const uint2*)th, wrp, wcol, wm_b2,
                                                 geh, GG, 0, NWM);
    // geh = graph_embeddings [NWM, G] fp16

    // ===== token concept sum + text conversion -> cat buffers =====
    gather4sum_h_kernel<<<(NF + 3) / 4, bSp>>>((const uint2*)geh, t2n, c1h, c3h, NF);
    textconv_kernel<<<(NF * PLM4 + 255) / 256, 256>>>((const float4*)text, c1h, c3h, NF);

    // ===== fc1 (2-pass, exact-B; fp16 output) =====
    wconv_kernel<<<dim3(GG / 32, CAT1 / 32), wcb>>>(fc1_W, p1h, p1l, CAT1, GG);
    mgemm<2>(c1h, p1h, p1l, fc1_b, nullptr, gteh, GG, NF, GG, CAT1);

    // ===== FSTM CSR + gather =====
    zero_int_kernel<<<(NF + 255) / 256, 256>>>(fcur, NF);
    hist_kernel<<<(EF + 255) / 256, 256>>>(f_ei + EF, fcur, EF);
    scan_kernel<<<1, 1024>>>(fcur, frp, NF, EF);
    fill_kernel<<<(EF + 255) / 256, 256>>>(f_ei, f_ei + EF, fcur, fcol, EF);
    gather_h_kernel<<<(NF + 3) / 4, bSp>>>((const uint2*)gteh, fids, (uint2*)ah, NF);

    // ===== FSTM layer 1 (2-pass, fp32 t) =====
    wconv_kernel<<<dim3(GG / 32, GG / 32), wcb>>>(f_W1, gh1, gl1, GG, GG);
    mgemm<2>(ah, gh1, gl1, zb, fM, nullptr, GG, NF, GG, GG);
    spmm_post_f32_kernel<<<(NF + 3) / 4, bSp>>>((const float4*)fM, frp, fcol, f_b1,
                                                ah, GG, 0, NF);
    // ===== FSTM layer 2 (2-pass; output straight into cat3 @ col 1024) =====
    wconv_kernel<<<dim3(GG / 32, GG / 32), wcb>>>(f_W2, gh2, gl2, GG, GG);
    mgemm<2>(ah, gh2, gl2, zb, fM, nullptr, GG, NF, GG, GG);
    spmm_post_f32_kernel<<<(NF + 3) / 4, bSp>>>((const float4*)fM, frp, fcol, f_b2,
                                                c3h, CAT3, PLM + GG, NF);

    // ===== fc3 -> out (1-pass) =====
    wconv_kernel<<<dim3(PLM / 32, CAT3 / 32), wcb>>>(fc3_W, p3h, nullptr, CAT3, PLM);
    mgemm<1>(c3h, p3h, nullptr, fc3_b, out, nullptr, PLM, NF, PLM, CAT3);
}